// round 7
// baseline (speedup 1.0000x reference)
#include <cuda_runtime.h>
#include <cuda_bf16.h>
#include <cstdint>
#include <math_constants.h>

#define N_VEC 65536
#define D 64
#define K 1024
#define MTILE 512
#define NBLK (N_VEC / MTILE)       // 128
#define MARGIN 4e-4f
#define OUT_E_OFF ((size_t)N_VEC * D)
#define OUT_S_OFF (OUT_E_OFF + (size_t)N_VEC * K)

#define APAD 72                    // bf16 elems per padded row (144B)
#define BPAD 72
// dynamic smem offsets (bytes)
#define OFF_SB  0                  // 4KB : g_B copy
#define OFF_IDX 4096               // 2KB : per-row argmin
#define OFF_RED 6144               // 64B : per-warp loss partials
#define OFF_A   6272               // 512*144 = 73728
#define OFF_B   80000              // 1024*144 = 147456
#define SMEM_TOTAL 227456

__device__ float  g_B[K];
__device__ __align__(16) __nv_bfloat16 g_ebf[K * BPAD];
__device__ int    g_cnt;
__device__ int    g_list[N_VEC];
__device__ int    g_idx[N_VEC];
__device__ float  g_part[NBLK];
__device__ float  g_fix;

// descending top-4 insert (S[0] best). strict > keeps earlier (lower-k) on ties.
#define INS4(S, I, s, i) { if ((s) > S[3]) { \
    if ((s) > S[2]) { S[3]=S[2]; I[3]=I[2]; \
        if ((s) > S[1]) { S[2]=S[1]; I[2]=I[1]; \
            if ((s) > S[0]) { S[1]=S[0]; I[1]=I[0]; S[0]=(s); I[0]=(i); } \
            else { S[1]=(s); I[1]=(i); } } \
        else { S[2]=(s); I[2]=(i); } } \
    else { S[3]=(s); I[3]=(i); } } }

#define MMA(c, a, bb0, bb1) asm volatile( \
    "mma.sync.aligned.m16n8k16.row.col.f32.bf16.bf16.f32 " \
    "{%0,%1,%2,%3}, {%4,%5,%6,%7}, {%8,%9}, {%0,%1,%2,%3};" \
    : "+f"(c[0]), "+f"(c[1]), "+f"(c[2]), "+f"(c[3]) \
    : "r"(a[0]), "r"(a[1]), "r"(a[2]), "r"(a[3]), "r"(bb0), "r"(bb1))

#define CSWP(a, b) { if ((a) > (b)) { int _t = (a); (a) = (b); (b) = _t; } }

// ---------------- prep: g_B (exact chain) + padded bf16 codebook ----------
__global__ void vq_prep(const float* __restrict__ emb) {
    int k = blockIdx.x * blockDim.x + threadIdx.x;    // 8 x 128 = 1024
    float v[D];
    const float4* r4 = (const float4*)(emb + (size_t)k * D);
    #pragma unroll
    for (int j = 0; j < 16; j++) {
        float4 t = r4[j];
        v[4*j] = t.x; v[4*j+1] = t.y; v[4*j+2] = t.z; v[4*j+3] = t.w;
    }
    float bb = 0.f;
    #pragma unroll
    for (int d = 0; d < D; d++) bb += v[d] * v[d];
    g_B[k] = bb;
    __nv_bfloat162* eb = (__nv_bfloat162*)(g_ebf + (size_t)k * BPAD);
    #pragma unroll
    for (int j = 0; j < 32; j++)
        eb[j] = __float22bfloat162_rn(make_float2(v[2*j], v[2*j+1]));
    #pragma unroll
    for (int j = 32; j < 36; j++)
        eb[j] = __float22bfloat162_rn(make_float2(0.f, 0.f));
    if (k == 0) { g_cnt = 0; g_fix = 0.f; }
}

// ---------------- main: HMMA prefilter + top4 + exact rescore -------------
__global__ __launch_bounds__(512, 1) void vq_main(
    const float* __restrict__ xg, const float* __restrict__ emb, float* __restrict__ out)
{
    extern __shared__ char sm[];
    float*    sB   = (float*)(sm + OFF_SB);
    int*      sIdx = (int*)(sm + OFF_IDX);
    float*    sW   = (float*)(sm + OFF_RED);
    uint32_t* Aw   = (uint32_t*)(sm + OFF_A);   // 36 words per padded row
    uint32_t* Bw   = (uint32_t*)(sm + OFF_B);

    const int tid = threadIdx.x;
    const int warp = tid >> 5, lane = tid & 31;
    const int g = lane >> 2, tig = lane & 3;
    const int n0 = blockIdx.x * MTILE;

    for (int i = tid; i < K; i += 512) sB[i] = g_B[i];
    { // stage A: x f32 -> bf16 padded rows
        const float4* x4 = (const float4*)(xg + (size_t)n0 * D);
        for (int i = tid; i < MTILE * 16; i += 512) {
            float4 v = x4[i];
            int row = i >> 4, j = i & 15;
            __nv_bfloat162* p =
                (__nv_bfloat162*)((__nv_bfloat16*)(sm + OFF_A) + row * APAD + j * 4);
            p[0] = __float22bfloat162_rn(make_float2(v.x, v.y));
            p[1] = __float22bfloat162_rn(make_float2(v.z, v.w));
        }
    }
    { // stage B: padded bf16 codebook copy
        const float4* e4 = (const float4*)g_ebf;
        float4* s4 = (float4*)(sm + OFF_B);
        for (int i = tid; i < (K * BPAD * 2) / 16; i += 512) s4[i] = e4[i];
    }
    __syncthreads();

    const int rbase = warp * 32;
    // preload A fragments: [rowtile][kstep][4 regs]
    uint32_t af[2][4][4];
    #pragma unroll
    for (int rt = 0; rt < 2; rt++) {
        int r0w = (rbase + rt * 16 + g) * 36;
        #pragma unroll
        for (int ks = 0; ks < 4; ks++) {
            int kw = ks * 8 + tig;
            af[rt][ks][0] = Aw[r0w + kw];
            af[rt][ks][1] = Aw[r0w + 288 + kw];      // +8 rows
            af[rt][ks][2] = Aw[r0w + kw + 4];
            af[rt][ks][3] = Aw[r0w + 288 + kw + 4];
        }
    }
    float TS[4][4]; int TI[4][4];
    #pragma unroll
    for (int j = 0; j < 4; j++)
        #pragma unroll
        for (int p = 0; p < 4; p++) { TS[j][p] = -CUDART_INF_F; TI[j][p] = 0; }

    for (int nt = 0; nt < 128; nt++) {
        const int nbase = nt * 8;
        uint32_t b0[4], b1[4];
        const int brw = (nbase + g) * 36;
        #pragma unroll
        for (int ks = 0; ks < 4; ks++) {
            b0[ks] = Bw[brw + ks * 8 + tig];
            b1[ks] = Bw[brw + ks * 8 + tig + 4];
        }
        float c0[4] = {0.f,0.f,0.f,0.f}, c1[4] = {0.f,0.f,0.f,0.f};
        #pragma unroll
        for (int ks = 0; ks < 4; ks++) {
            MMA(c0, af[0][ks], b0[ks], b1[ks]);
            MMA(c1, af[1][ks], b0[ks], b1[ks]);
        }
        const int k0i = nbase + tig * 2;
        const float Bc0 = sB[k0i], Bc1 = sB[k0i + 1];
        // scores (proxy = 2*dot - ||e||^2); gated inserts (gate skips only no-ops)
        {
            float sa = fmaf(2.f, c0[0], -Bc0), sb2 = fmaf(2.f, c0[1], -Bc1);
            if (fmaxf(sa, sb2) > TS[0][3]) { INS4(TS[0], TI[0], sa, k0i); INS4(TS[0], TI[0], sb2, k0i+1); }
        }
        {
            float sa = fmaf(2.f, c0[2], -Bc0), sb2 = fmaf(2.f, c0[3], -Bc1);
            if (fmaxf(sa, sb2) > TS[1][3]) { INS4(TS[1], TI[1], sa, k0i); INS4(TS[1], TI[1], sb2, k0i+1); }
        }
        {
            float sa = fmaf(2.f, c1[0], -Bc0), sb2 = fmaf(2.f, c1[1], -Bc1);
            if (fmaxf(sa, sb2) > TS[2][3]) { INS4(TS[2], TI[2], sa, k0i); INS4(TS[2], TI[2], sb2, k0i+1); }
        }
        {
            float sa = fmaf(2.f, c1[2], -Bc0), sb2 = fmaf(2.f, c1[3], -Bc1);
            if (fmaxf(sa, sb2) > TS[3][3]) { INS4(TS[3], TI[3], sa, k0i); INS4(TS[3], TI[3], sb2, k0i+1); }
        }
    }
    // quad merge (lanes in a quad own the same 4 rows, disjoint cols)
    #pragma unroll
    for (int dd = 1; dd <= 2; dd <<= 1) {
        #pragma unroll
        for (int j = 0; j < 4; j++) {
            float ns[4]; int ni[4];
            #pragma unroll
            for (int p = 0; p < 4; p++) {
                ns[p] = __shfl_xor_sync(0xffffffffu, TS[j][p], dd);
                ni[p] = __shfl_xor_sync(0xffffffffu, TI[j][p], dd);
            }
            #pragma unroll
            for (int p = 0; p < 4; p++) INS4(TS[j], TI[j], ns[p], ni[p]);
        }
    }
    // this thread owns row slot j == tig  (row = g + tig*8 within warp)
    const int rowp = rbase + g + tig * 8;
    const int n = n0 + rowp;
    float cs[4]; int ci[4];
    #pragma unroll
    for (int j = 0; j < 4; j++) if (tig == j) {
        #pragma unroll
        for (int p = 0; p < 4; p++) { cs[p] = TS[j][p]; ci[p] = TI[j][p]; }
    }
    const bool fb = (cs[3] >= cs[0] - MARGIN);
    CSWP(ci[0], ci[1]); CSWP(ci[2], ci[3]);
    CSWP(ci[0], ci[2]); CSWP(ci[1], ci[3]); CSWP(ci[1], ci[2]);

    // exact rescore (validated round-0 fl chain, ascending-k strict <)
    float xv[64];
    {
        const float4* xr = (const float4*)(xg + (size_t)n * D);
        #pragma unroll
        for (int j = 0; j < 16; j++) {
            float4 v = xr[j];
            xv[4*j] = v.x; xv[4*j+1] = v.y; xv[4*j+2] = v.z; xv[4*j+3] = v.w;
        }
    }
    float Av = 0.f;
    #pragma unroll
    for (int d = 0; d < D; d++) Av = fmaf(xv[d], xv[d], Av);
    float best = CUDART_INF_F; int bidx = 0;
    #pragma unroll
    for (int q = 0; q < 4; q++) {
        int idx = ci[q];
        const float4* er = (const float4*)(emb + (size_t)idx * D);
        float a = 0.f;
        #pragma unroll
        for (int j = 0; j < 16; j++) {
            float4 v = er[j];
            a = fmaf(xv[4*j],   v.x, a);
            a = fmaf(xv[4*j+1], v.y, a);
            a = fmaf(xv[4*j+2], v.z, a);
            a = fmaf(xv[4*j+3], v.w, a);
        }
        float ddv = (Av + sB[idx]) - 2.f * a;
        if (ddv < best) { best = ddv; bidx = idx; }
    }
    if (fb) { int sl = atomicAdd(&g_cnt, 1); g_list[sl] = n; }
    sIdx[rowp] = bidx;
    __syncthreads();

    // g_idx coalesced
    g_idx[n0 + tid] = sIdx[tid];

    // quantized_st + per-vector loss: LINEAR coalesced loop (L2-friendly)
    float ls = 0.f;
    {
        const float4* x4 = (const float4*)(xg + (size_t)n0 * D);
        float4* qo = (float4*)(out + (size_t)n0 * D);
        #pragma unroll
        for (int it = 0; it < 16; it++) {
            int i = tid + it * 512;
            int r = i >> 4, c4 = i & 15;
            int idx = sIdx[r];
            float4 xw = x4[i];
            float4 e4 = ((const float4*)(emb + (size_t)idx * D))[c4];
            float dx = e4.x - xw.x, dy = e4.y - xw.y;
            float dz = e4.z - xw.z, dw = e4.w - xw.w;
            float4 o4 = make_float4(xw.x + dx, xw.y + dy, xw.z + dz, xw.w + dw);
            __stcs(&qo[i], o4);
            ls += dx*dx + dy*dy + dz*dz + dw*dw;
        }
    }
    // block loss reduction: intra-warp shfl, then warp leaders
    #pragma unroll
    for (int o = 16; o; o >>= 1) ls += __shfl_down_sync(0xffffffffu, ls, o);
    if (lane == 0) sW[warp] = ls;
    __syncthreads();
    if (tid == 0) {
        float s = 0.f;
        #pragma unroll
        for (int w = 0; w < 16; w++) s += sW[w];
        g_part[blockIdx.x] = s;
    }
}

// ---------------- fallback: warp-per-vector exact scan (L2-direct) --------
// Corrects g_idx / quantized_st / loss BEFORE vq_onehot runs (no row rewrite).
__global__ __launch_bounds__(256) void vq_fallback(
    const float* __restrict__ xg, const float* __restrict__ emb, float* __restrict__ out)
{
    const int cnt = g_cnt;
    const int gw = (blockIdx.x * 256 + threadIdx.x) >> 5;     // 2048 warps
    const int lane = threadIdx.x & 31;
    for (int it = gw; it < cnt; it += 2048) {
        const int n = g_list[it];
        float xv[64];
        {
            const float4* xr = (const float4*)(xg + (size_t)n * D);
            #pragma unroll
            for (int j = 0; j < 16; j++) {
                float4 v = xr[j];
                xv[4*j] = v.x; xv[4*j+1] = v.y; xv[4*j+2] = v.z; xv[4*j+3] = v.w;
            }
        }
        float Av = 0.f;
        #pragma unroll
        for (int d = 0; d < D; d++) Av = fmaf(xv[d], xv[d], Av);
        // each lane scans 32 codes straight from L2 (codebook is hot)
        float best = CUDART_INF_F; int bidx = 0;
        const int k0 = lane * 32;
        #pragma unroll 2
        for (int kk = 0; kk < 32; kk++) {
            const int k = k0 + kk;
            const float4* er = (const float4*)(emb + (size_t)k * D);
            float a = 0.f;
            #pragma unroll
            for (int j = 0; j < 16; j++) {
                float4 v = er[j];
                a = fmaf(xv[4*j],   v.x, a);
                a = fmaf(xv[4*j+1], v.y, a);
                a = fmaf(xv[4*j+2], v.z, a);
                a = fmaf(xv[4*j+3], v.w, a);
            }
            float ddv = (Av + g_B[k]) - 2.f * a;
            if (ddv < best) { best = ddv; bidx = k; }
        }
        // warp-min with lowest-k tie-break (float then index, both ascending)
        unsigned long long key =
            ((unsigned long long)__float_as_uint(best) << 32) | (unsigned)bidx;
        #pragma unroll
        for (int o = 16; o; o >>= 1) {
            unsigned long long k2 = __shfl_down_sync(0xffffffffu, key, o);
            if (k2 < key) key = k2;
        }
        key = __shfl_sync(0xffffffffu, key, 0);
        const int idx = (int)(key & 0xffffffffu);
        const int old = g_idx[n];
        if (idx != old) {
            if (lane == 0) g_idx[n] = idx;
            float lsn = 0.f, lso = 0.f;
            if (lane < 16) {
                float4 e4 = ((const float4*)(emb + (size_t)idx * D))[lane];
                float4 o4 = ((const float4*)(emb + (size_t)old * D))[lane];
                float xx = xv[4*lane], xy = xv[4*lane+1], xz = xv[4*lane+2], xw2 = xv[4*lane+3];
                float dx = e4.x-xx, dy = e4.y-xy, dz = e4.z-xz, dw = e4.w-xw2;
                ((float4*)(out + (size_t)n * D))[lane] =
                    make_float4(xx+dx, xy+dy, xz+dz, xw2+dw);
                lsn = dx*dx + dy*dy + dz*dz + dw*dw;
                float ox = o4.x-xx, oy = o4.y-xy, oz = o4.z-xz, ow = o4.w-xw2;
                lso = ox*ox + oy*oy + oz*oz + ow*ow;
            }
            #pragma unroll
            for (int o = 16; o; o >>= 1) {
                lsn += __shfl_down_sync(0xffffffffu, lsn, o);
                lso += __shfl_down_sync(0xffffffffu, lso, o);
            }
            if (lane == 0) atomicAdd(&g_fix, lsn - lso);
        }
    }
}

// ---------------- one-hot encodings: dedicated streaming kernel -----------
__global__ __launch_bounds__(256) void vq_onehot(float* __restrict__ out) {
    __shared__ int sI[32];
    const int r0 = blockIdx.x * 32;       // grid 2048
    if (threadIdx.x < 32) sI[threadIdx.x] = g_idx[r0 + threadIdx.x];
    __syncthreads();
    float* eout = out + OUT_E_OFF;
    #pragma unroll 4
    for (int i = threadIdx.x; i < 32 * 256; i += 256) {
        int r = i >> 8, c4 = i & 255;
        int idx = sI[r];
        float4 v = make_float4(0.f, 0.f, 0.f, 0.f);
        if ((idx >> 2) == c4) ((float*)&v)[idx & 3] = 1.f;
        __stcs(&((float4*)(eout + (size_t)(r0 + r) * K))[c4], v);
    }
}

// ---------------- finalize: 128 partials + fix ----------------------------
__global__ void vq_finalize(float* __restrict__ out) {
    __shared__ double sR[128];
    int tid = threadIdx.x;   // 128
    sR[tid] = (double)g_part[tid];
    __syncthreads();
    #pragma unroll
    for (int st = 64; st; st >>= 1) {
        if (tid < st) sR[tid] += sR[tid + st];
        __syncthreads();
    }
    if (tid == 0) {
        double tot = sR[0] + (double)g_fix;
        float cb = (float)(tot / (double)((size_t)N_VEC * D));
        out[OUT_S_OFF + 0] = cb + 0.25f * cb;
        out[OUT_S_OFF + 1] = cb;
        out[OUT_S_OFF + 2] = cb;
    }
}

extern "C" void kernel_launch(void* const* d_in, const int* in_sizes, int n_in,
                              void* d_out, int out_size) {
    const float* x   = (const float*)d_in[0];
    const float* emb = (const float*)d_in[1];
    float* out = (float*)d_out;
    cudaFuncSetAttribute(vq_main, cudaFuncAttributeMaxDynamicSharedMemorySize, SMEM_TOTAL);
    vq_prep<<<8, 128>>>(emb);
    vq_main<<<NBLK, 512, SMEM_TOTAL>>>(x, emb, out);
    vq_fallback<<<256, 256>>>(x, emb, out);
    vq_onehot<<<N_VEC / 32, 256>>>(out);
    vq_finalize<<<1, 128>>>(out);
}

// round 8
// speedup vs baseline: 1.0015x; 1.0015x over previous
#include <cuda_runtime.h>
#include <cuda_fp16.h>
#include <cstdint>
#include <math_constants.h>

#define N_VEC 65536
#define D 64
#define K 1024
#define MTILE 512
#define NBLK (N_VEC / MTILE)       // 128
#define MARGIN 1.25e-4f
#define OUT_E_OFF ((size_t)N_VEC * D)
#define OUT_S_OFF (OUT_E_OFF + (size_t)N_VEC * K)

#define APAD 72                    // fp16 elems per padded row (144B)
#define BPAD 72
// dynamic smem offsets (bytes)
#define OFF_SB  0                  // 4KB : g_B copy
#define OFF_IDX 4096               // 2KB : per-row argmin
#define OFF_RED 6144               // 64B : per-warp loss partials
#define OFF_A   6272               // 512*144 = 73728
#define OFF_B   80000              // 1024*144 = 147456
#define SMEM_TOTAL 227456

__device__ float  g_B[K];
__device__ __align__(16) __half g_ehf[K * BPAD];
__device__ int    g_cnt;
__device__ int    g_list[N_VEC];
__device__ int    g_idx[N_VEC];
__device__ float  g_part[NBLK];
__device__ float  g_fix;

// descending top-4 insert (S[0] best). strict > keeps earlier (lower-k) on ties.
#define INS4(S, I, s, i) { if ((s) > S[3]) { \
    if ((s) > S[2]) { S[3]=S[2]; I[3]=I[2]; \
        if ((s) > S[1]) { S[2]=S[1]; I[2]=I[1]; \
            if ((s) > S[0]) { S[1]=S[0]; I[1]=I[0]; S[0]=(s); I[0]=(i); } \
            else { S[1]=(s); I[1]=(i); } } \
        else { S[2]=(s); I[2]=(i); } } \
    else { S[3]=(s); I[3]=(i); } } }

#define MMA(c, a, bb0, bb1) asm volatile( \
    "mma.sync.aligned.m16n8k16.row.col.f32.f16.f16.f32 " \
    "{%0,%1,%2,%3}, {%4,%5,%6,%7}, {%8,%9}, {%0,%1,%2,%3};" \
    : "+f"(c[0]), "+f"(c[1]), "+f"(c[2]), "+f"(c[3]) \
    : "r"(a[0]), "r"(a[1]), "r"(a[2]), "r"(a[3]), "r"(bb0), "r"(bb1))

#define CSWP(a, b) { if ((a) > (b)) { int _t = (a); (a) = (b); (b) = _t; } }

// ---------------- prep: g_B (exact chain) + padded fp16 codebook ----------
__global__ void vq_prep(const float* __restrict__ emb) {
    int k = blockIdx.x * blockDim.x + threadIdx.x;    // 8 x 128 = 1024
    float v[D];
    const float4* r4 = (const float4*)(emb + (size_t)k * D);
    #pragma unroll
    for (int j = 0; j < 16; j++) {
        float4 t = r4[j];
        v[4*j] = t.x; v[4*j+1] = t.y; v[4*j+2] = t.z; v[4*j+3] = t.w;
    }
    float bb = 0.f;
    #pragma unroll
    for (int d = 0; d < D; d++) bb += v[d] * v[d];
    g_B[k] = bb;
    __half2* eb = (__half2*)(g_ehf + (size_t)k * BPAD);
    #pragma unroll
    for (int j = 0; j < 32; j++)
        eb[j] = __floats2half2_rn(v[2*j], v[2*j+1]);
    #pragma unroll
    for (int j = 32; j < 36; j++)
        eb[j] = __floats2half2_rn(0.f, 0.f);
    if (k == 0) { g_cnt = 0; g_fix = 0.f; }
}

// ---------------- main: HMMA(fp16) prefilter + top4 + exact rescore -------
__global__ __launch_bounds__(512, 1) void vq_main(
    const float* __restrict__ xg, const float* __restrict__ emb, float* __restrict__ out)
{
    extern __shared__ char sm[];
    float*    sB   = (float*)(sm + OFF_SB);
    int*      sIdx = (int*)(sm + OFF_IDX);
    float*    sW   = (float*)(sm + OFF_RED);
    uint32_t* Aw   = (uint32_t*)(sm + OFF_A);   // 36 words per padded row
    uint32_t* Bw   = (uint32_t*)(sm + OFF_B);

    const int tid = threadIdx.x;
    const int warp = tid >> 5, lane = tid & 31;
    const int g = lane >> 2, tig = lane & 3;
    const int n0 = blockIdx.x * MTILE;

    for (int i = tid; i < K; i += 512) sB[i] = g_B[i];
    { // stage A: x f32 -> fp16 padded rows
        const float4* x4 = (const float4*)(xg + (size_t)n0 * D);
        for (int i = tid; i < MTILE * 16; i += 512) {
            float4 v = x4[i];
            int row = i >> 4, j = i & 15;
            __half2* p = (__half2*)((__half*)(sm + OFF_A) + row * APAD + j * 4);
            p[0] = __floats2half2_rn(v.x, v.y);
            p[1] = __floats2half2_rn(v.z, v.w);
        }
    }
    { // stage B: padded fp16 codebook copy
        const float4* e4 = (const float4*)g_ehf;
        float4* s4 = (float4*)(sm + OFF_B);
        for (int i = tid; i < (K * BPAD * 2) / 16; i += 512) s4[i] = e4[i];
    }
    __syncthreads();

    const int rbase = warp * 32;
    // preload A fragments: [rowtile][kstep][4 regs]
    uint32_t af[2][4][4];
    #pragma unroll
    for (int rt = 0; rt < 2; rt++) {
        int r0w = (rbase + rt * 16 + g) * 36;
        #pragma unroll
        for (int ks = 0; ks < 4; ks++) {
            int kw = ks * 8 + tig;
            af[rt][ks][0] = Aw[r0w + kw];
            af[rt][ks][1] = Aw[r0w + 288 + kw];      // +8 rows
            af[rt][ks][2] = Aw[r0w + kw + 4];
            af[rt][ks][3] = Aw[r0w + 288 + kw + 4];
        }
    }
    float TS[4][4]; int TI[4][4];
    #pragma unroll
    for (int j = 0; j < 4; j++)
        #pragma unroll
        for (int p = 0; p < 4; p++) { TS[j][p] = -CUDART_INF_F; TI[j][p] = 0; }

    for (int nt = 0; nt < 128; nt++) {
        const int nbase = nt * 8;
        uint32_t b0[4], b1[4];
        const int brw = (nbase + g) * 36;
        #pragma unroll
        for (int ks = 0; ks < 4; ks++) {
            b0[ks] = Bw[brw + ks * 8 + tig];
            b1[ks] = Bw[brw + ks * 8 + tig + 4];
        }
        float c0[4] = {0.f,0.f,0.f,0.f}, c1[4] = {0.f,0.f,0.f,0.f};
        #pragma unroll
        for (int ks = 0; ks < 4; ks++) {
            MMA(c0, af[0][ks], b0[ks], b1[ks]);
            MMA(c1, af[1][ks], b0[ks], b1[ks]);
        }
        const int k0i = nbase + tig * 2;
        const float Bc0 = sB[k0i], Bc1 = sB[k0i + 1];
        // scores (proxy = 2*dot - ||e||^2); gated inserts (gate skips only no-ops)
        {
            float sa = fmaf(2.f, c0[0], -Bc0), sb2 = fmaf(2.f, c0[1], -Bc1);
            if (fmaxf(sa, sb2) > TS[0][3]) { INS4(TS[0], TI[0], sa, k0i); INS4(TS[0], TI[0], sb2, k0i+1); }
        }
        {
            float sa = fmaf(2.f, c0[2], -Bc0), sb2 = fmaf(2.f, c0[3], -Bc1);
            if (fmaxf(sa, sb2) > TS[1][3]) { INS4(TS[1], TI[1], sa, k0i); INS4(TS[1], TI[1], sb2, k0i+1); }
        }
        {
            float sa = fmaf(2.f, c1[0], -Bc0), sb2 = fmaf(2.f, c1[1], -Bc1);
            if (fmaxf(sa, sb2) > TS[2][3]) { INS4(TS[2], TI[2], sa, k0i); INS4(TS[2], TI[2], sb2, k0i+1); }
        }
        {
            float sa = fmaf(2.f, c1[2], -Bc0), sb2 = fmaf(2.f, c1[3], -Bc1);
            if (fmaxf(sa, sb2) > TS[3][3]) { INS4(TS[3], TI[3], sa, k0i); INS4(TS[3], TI[3], sb2, k0i+1); }
        }
    }
    // quad merge (lanes in a quad own the same 4 rows, disjoint cols)
    #pragma unroll
    for (int dd = 1; dd <= 2; dd <<= 1) {
        #pragma unroll
        for (int j = 0; j < 4; j++) {
            float ns[4]; int ni[4];
            #pragma unroll
            for (int p = 0; p < 4; p++) {
                ns[p] = __shfl_xor_sync(0xffffffffu, TS[j][p], dd);
                ni[p] = __shfl_xor_sync(0xffffffffu, TI[j][p], dd);
            }
            #pragma unroll
            for (int p = 0; p < 4; p++) INS4(TS[j], TI[j], ns[p], ni[p]);
        }
    }
    // this thread owns row slot j == tig  (row = g + tig*8 within warp)
    const int rowp = rbase + g + tig * 8;
    const int n = n0 + rowp;
    float cs[4]; int ci[4];
    #pragma unroll
    for (int j = 0; j < 4; j++) if (tig == j) {
        #pragma unroll
        for (int p = 0; p < 4; p++) { cs[p] = TS[j][p]; ci[p] = TI[j][p]; }
    }
    const bool fb = (cs[3] >= cs[0] - MARGIN);
    CSWP(ci[0], ci[1]); CSWP(ci[2], ci[3]);
    CSWP(ci[0], ci[2]); CSWP(ci[1], ci[3]); CSWP(ci[1], ci[2]);

    // exact rescore (validated round-0 fl chain, ascending-k strict <)
    float xv[64];
    {
        const float4* xr = (const float4*)(xg + (size_t)n * D);
        #pragma unroll
        for (int j = 0; j < 16; j++) {
            float4 v = xr[j];
            xv[4*j] = v.x; xv[4*j+1] = v.y; xv[4*j+2] = v.z; xv[4*j+3] = v.w;
        }
    }
    float Av = 0.f;
    #pragma unroll
    for (int d = 0; d < D; d++) Av = fmaf(xv[d], xv[d], Av);
    float best = CUDART_INF_F; int bidx = 0;
    #pragma unroll
    for (int q = 0; q < 4; q++) {
        int idx = ci[q];
        const float4* er = (const float4*)(emb + (size_t)idx * D);
        float a = 0.f;
        #pragma unroll
        for (int j = 0; j < 16; j++) {
            float4 v = er[j];
            a = fmaf(xv[4*j],   v.x, a);
            a = fmaf(xv[4*j+1], v.y, a);
            a = fmaf(xv[4*j+2], v.z, a);
            a = fmaf(xv[4*j+3], v.w, a);
        }
        float ddv = (Av + sB[idx]) - 2.f * a;
        if (ddv < best) { best = ddv; bidx = idx; }
    }
    if (fb) { int sl = atomicAdd(&g_cnt, 1); g_list[sl] = n; }
    sIdx[rowp] = bidx;
    __syncthreads();

    // g_idx coalesced
    g_idx[n0 + tid] = sIdx[tid];

    // quantized_st + per-vector loss: LINEAR coalesced loop (L2-friendly)
    float ls = 0.f;
    {
        const float4* x4 = (const float4*)(xg + (size_t)n0 * D);
        float4* qo = (float4*)(out + (size_t)n0 * D);
        #pragma unroll
        for (int it = 0; it < 16; it++) {
            int i = tid + it * 512;
            int r = i >> 4, c4 = i & 15;
            int idx = sIdx[r];
            float4 xw = x4[i];
            float4 e4 = ((const float4*)(emb + (size_t)idx * D))[c4];
            float dx = e4.x - xw.x, dy = e4.y - xw.y;
            float dz = e4.z - xw.z, dw = e4.w - xw.w;
            float4 o4 = make_float4(xw.x + dx, xw.y + dy, xw.z + dz, xw.w + dw);
            __stcs(&qo[i], o4);
            ls += dx*dx + dy*dy + dz*dz + dw*dw;
        }
    }
    // block loss reduction: intra-warp shfl, then warp leaders
    #pragma unroll
    for (int o = 16; o; o >>= 1) ls += __shfl_down_sync(0xffffffffu, ls, o);
    if (lane == 0) sW[warp] = ls;
    __syncthreads();
    if (tid == 0) {
        float s = 0.f;
        #pragma unroll
        for (int w = 0; w < 16; w++) s += sW[w];
        g_part[blockIdx.x] = s;
    }
}

// ---------------- fallback: warp-per-vector exact scan (L2-direct) --------
// Corrects g_idx / quantized_st / loss BEFORE vq_onehot runs.
__global__ __launch_bounds__(256) void vq_fallback(
    const float* __restrict__ xg, const float* __restrict__ emb, float* __restrict__ out)
{
    const int cnt = g_cnt;
    const int gw = (blockIdx.x * 256 + threadIdx.x) >> 5;     // 2048 warps
    const int lane = threadIdx.x & 31;
    for (int it = gw; it < cnt; it += 2048) {
        const int n = g_list[it];
        float xv[64];
        {
            const float4* xr = (const float4*)(xg + (size_t)n * D);
            #pragma unroll
            for (int j = 0; j < 16; j++) {
                float4 v = xr[j];
                xv[4*j] = v.x; xv[4*j+1] = v.y; xv[4*j+2] = v.z; xv[4*j+3] = v.w;
            }
        }
        float Av = 0.f;
        #pragma unroll
        for (int d = 0; d < D; d++) Av = fmaf(xv[d], xv[d], Av);
        // each lane scans 32 codes straight from L2 (codebook is hot)
        float best = CUDART_INF_F; int bidx = 0;
        const int k0 = lane * 32;
        #pragma unroll 2
        for (int kk = 0; kk < 32; kk++) {
            const int k = k0 + kk;
            const float4* er = (const float4*)(emb + (size_t)k * D);
            float a = 0.f;
            #pragma unroll
            for (int j = 0; j < 16; j++) {
                float4 v = er[j];
                a = fmaf(xv[4*j],   v.x, a);
                a = fmaf(xv[4*j+1], v.y, a);
                a = fmaf(xv[4*j+2], v.z, a);
                a = fmaf(xv[4*j+3], v.w, a);
            }
            float ddv = (Av + g_B[k]) - 2.f * a;
            if (ddv < best) { best = ddv; bidx = k; }
        }
        // warp-min with lowest-k tie-break (float then index, both ascending)
        unsigned long long key =
            ((unsigned long long)__float_as_uint(best) << 32) | (unsigned)bidx;
        #pragma unroll
        for (int o = 16; o; o >>= 1) {
            unsigned long long k2 = __shfl_down_sync(0xffffffffu, key, o);
            if (k2 < key) key = k2;
        }
        key = __shfl_sync(0xffffffffu, key, 0);
        const int idx = (int)(key & 0xffffffffu);
        const int old = g_idx[n];
        if (idx != old) {
            if (lane == 0) g_idx[n] = idx;
            float lsn = 0.f, lso = 0.f;
            if (lane < 16) {
                float4 e4 = ((const float4*)(emb + (size_t)idx * D))[lane];
                float4 o4 = ((const float4*)(emb + (size_t)old * D))[lane];
                float xx = xv[4*lane], xy = xv[4*lane+1], xz = xv[4*lane+2], xw2 = xv[4*lane+3];
                float dx = e4.x-xx, dy = e4.y-xy, dz = e4.z-xz, dw = e4.w-xw2;
                ((float4*)(out + (size_t)n * D))[lane] =
                    make_float4(xx+dx, xy+dy, xz+dz, xw2+dw);
                lsn = dx*dx + dy*dy + dz*dz + dw*dw;
                float ox = o4.x-xx, oy = o4.y-xy, oz = o4.z-xz, ow = o4.w-xw2;
                lso = ox*ox + oy*oy + oz*oz + ow*ow;
            }
            #pragma unroll
            for (int o = 16; o; o >>= 1) {
                lsn += __shfl_down_sync(0xffffffffu, lsn, o);
                lso += __shfl_down_sync(0xffffffffu, lso, o);
            }
            if (lane == 0) atomicAdd(&g_fix, lsn - lso);
        }
    }
}

// ---------------- one-hot encodings: dedicated streaming kernel -----------
__global__ __launch_bounds__(256) void vq_onehot(float* __restrict__ out) {
    __shared__ int sI[32];
    const int r0 = blockIdx.x * 32;       // grid 2048
    if (threadIdx.x < 32) sI[threadIdx.x] = g_idx[r0 + threadIdx.x];
    __syncthreads();
    float* eout = out + OUT_E_OFF;
    #pragma unroll 4
    for (int i = threadIdx.x; i < 32 * 256; i += 256) {
        int r = i >> 8, c4 = i & 255;
        int idx = sI[r];
        float4 v = make_float4(0.f, 0.f, 0.f, 0.f);
        if ((idx >> 2) == c4) ((float*)&v)[idx & 3] = 1.f;
        __stcs(&((float4*)(eout + (size_t)(r0 + r) * K))[c4], v);
    }
}

// ---------------- finalize: 128 partials + fix ----------------------------
__global__ void vq_finalize(float* __restrict__ out) {
    __shared__ double sR[128];
    int tid = threadIdx.x;   // 128
    sR[tid] = (double)g_part[tid];
    __syncthreads();
    #pragma unroll
    for (int st = 64; st; st >>= 1) {
        if (tid < st) sR[tid] += sR[tid + st];
        __syncthreads();
    }
    if (tid == 0) {
        double tot = sR[0] + (double)g_fix;
        float cb = (float)(tot / (double)((size_t)N_VEC * D));
        out[OUT_S_OFF + 0] = cb + 0.25f * cb;
        out[OUT_S_OFF + 1] = cb;
        out[OUT_S_OFF + 2] = cb;
    }
}

extern "C" void kernel_launch(void* const* d_in, const int* in_sizes, int n_in,
                              void* d_out, int out_size) {
    const float* x   = (const float*)d_in[0];
    const float* emb = (const float*)d_in[1];
    float* out = (float*)d_out;
    cudaFuncSetAttribute(vq_main, cudaFuncAttributeMaxDynamicSharedMemorySize, SMEM_TOTAL);
    vq_prep<<<8, 128>>>(emb);
    vq_main<<<NBLK, 512, SMEM_TOTAL>>>(x, emb, out);
    vq_fallback<<<256, 256>>>(x, emb, out);
    vq_onehot<<<N_VEC / 32, 256>>>(out);
    vq_finalize<<<1, 128>>>(out);
}

// round 9
// speedup vs baseline: 1.2828x; 1.2809x over previous
#include <cuda_runtime.h>
#include <cuda_fp16.h>
#include <cstdint>
#include <math_constants.h>

#define N_VEC 65536
#define D 64
#define K 1024
#define MTILE 512
#define NBLK (N_VEC / MTILE)       // 128
#define MARGIN 3e-5f
#define OUT_E_OFF ((size_t)N_VEC * D)
#define OUT_S_OFF (OUT_E_OFF + (size_t)N_VEC * K)

#define APAD 72                    // fp16 elems per padded row (144B)
#define BPAD 72
// dynamic smem offsets (bytes)
#define OFF_SB  0                  // 4KB : g_B copy
#define OFF_IDX 4096               // 2KB : per-row argmin
#define OFF_RED 6144               // 64B : per-warp loss partials
#define OFF_A   6272               // 512*144 = 73728
#define OFF_B   80000              // 1024*144 = 147456
#define SMEM_TOTAL 227456

__device__ float  g_B[K];
__device__ __align__(16) __half g_ehf[K * BPAD];
__device__ int    g_cnt;
__device__ int    g_list[N_VEC];
__device__ int    g_idx[N_VEC];
__device__ float  g_part[NBLK];
__device__ float  g_fix;

// descending top-4 insert (S[0] best). strict > keeps earlier (lower-k) on ties.
#define INS4(S, I, s, i) { if ((s) > S[3]) { \
    if ((s) > S[2]) { S[3]=S[2]; I[3]=I[2]; \
        if ((s) > S[1]) { S[2]=S[1]; I[2]=I[1]; \
            if ((s) > S[0]) { S[1]=S[0]; I[1]=I[0]; S[0]=(s); I[0]=(i); } \
            else { S[1]=(s); I[1]=(i); } } \
        else { S[2]=(s); I[2]=(i); } } \
    else { S[3]=(s); I[3]=(i); } } }

#define MMA(c, a, bb0, bb1) asm volatile( \
    "mma.sync.aligned.m16n8k16.row.col.f32.f16.f16.f32 " \
    "{%0,%1,%2,%3}, {%4,%5,%6,%7}, {%8,%9}, {%0,%1,%2,%3};" \
    : "+f"(c[0]), "+f"(c[1]), "+f"(c[2]), "+f"(c[3]) \
    : "r"(a[0]), "r"(a[1]), "r"(a[2]), "r"(a[3]), "r"(bb0), "r"(bb1))

#define CSWP(a, b) { if ((a) > (b)) { int _t = (a); (a) = (b); (b) = _t; } }

// ---------------- prep: g_B (exact chain) + padded fp16 codebook ----------
__global__ void vq_prep(const float* __restrict__ emb) {
    int k = blockIdx.x * blockDim.x + threadIdx.x;    // 8 x 128 = 1024
    float v[D];
    const float4* r4 = (const float4*)(emb + (size_t)k * D);
    #pragma unroll
    for (int j = 0; j < 16; j++) {
        float4 t = r4[j];
        v[4*j] = t.x; v[4*j+1] = t.y; v[4*j+2] = t.z; v[4*j+3] = t.w;
    }
    float bb = 0.f;
    #pragma unroll
    for (int d = 0; d < D; d++) bb += v[d] * v[d];
    g_B[k] = bb;
    __half2* eb = (__half2*)(g_ehf + (size_t)k * BPAD);
    #pragma unroll
    for (int j = 0; j < 32; j++)
        eb[j] = __floats2half2_rn(v[2*j], v[2*j+1]);
    #pragma unroll
    for (int j = 32; j < 36; j++)
        eb[j] = __floats2half2_rn(0.f, 0.f);
    if (k == 0) { g_cnt = 0; g_fix = 0.f; }
}

// ---------------- main: HMMA(fp16) prefilter + top4 + exact rescore -------
__global__ __launch_bounds__(512, 1) void vq_main(
    const float* __restrict__ xg, const float* __restrict__ emb, float* __restrict__ out)
{
    extern __shared__ char sm[];
    float*    sB   = (float*)(sm + OFF_SB);
    int*      sIdx = (int*)(sm + OFF_IDX);
    float*    sW   = (float*)(sm + OFF_RED);
    uint32_t* Aw   = (uint32_t*)(sm + OFF_A);   // 36 words per padded row
    uint32_t* Bw   = (uint32_t*)(sm + OFF_B);

    const int tid = threadIdx.x;
    const int warp = tid >> 5, lane = tid & 31;
    const int g = lane >> 2, tig = lane & 3;
    const int n0 = blockIdx.x * MTILE;

    for (int i = tid; i < K; i += 512) sB[i] = g_B[i];
    { // stage A: x f32 -> fp16 padded rows
        const float4* x4 = (const float4*)(xg + (size_t)n0 * D);
        for (int i = tid; i < MTILE * 16; i += 512) {
            float4 v = x4[i];
            int row = i >> 4, j = i & 15;
            __half2* p = (__half2*)((__half*)(sm + OFF_A) + row * APAD + j * 4);
            p[0] = __floats2half2_rn(v.x, v.y);
            p[1] = __floats2half2_rn(v.z, v.w);
        }
    }
    { // stage B: padded fp16 codebook copy
        const float4* e4 = (const float4*)g_ehf;
        float4* s4 = (float4*)(sm + OFF_B);
        for (int i = tid; i < (K * BPAD * 2) / 16; i += 512) s4[i] = e4[i];
    }
    __syncthreads();

    const int rbase = warp * 32;
    // preload A fragments: [rowtile][kstep][4 regs]
    uint32_t af[2][4][4];
    #pragma unroll
    for (int rt = 0; rt < 2; rt++) {
        int r0w = (rbase + rt * 16 + g) * 36;
        #pragma unroll
        for (int ks = 0; ks < 4; ks++) {
            int kw = ks * 8 + tig;
            af[rt][ks][0] = Aw[r0w + kw];
            af[rt][ks][1] = Aw[r0w + 288 + kw];      // +8 rows
            af[rt][ks][2] = Aw[r0w + kw + 4];
            af[rt][ks][3] = Aw[r0w + 288 + kw + 4];
        }
    }
    float TS[4][4]; int TI[4][4];
    #pragma unroll
    for (int j = 0; j < 4; j++)
        #pragma unroll
        for (int p = 0; p < 4; p++) { TS[j][p] = -CUDART_INF_F; TI[j][p] = 0; }

    for (int nt = 0; nt < 128; nt++) {
        const int nbase = nt * 8;
        uint32_t b0[4], b1[4];
        const int brw = (nbase + g) * 36;
        #pragma unroll
        for (int ks = 0; ks < 4; ks++) {
            b0[ks] = Bw[brw + ks * 8 + tig];
            b1[ks] = Bw[brw + ks * 8 + tig + 4];
        }
        float c0[4] = {0.f,0.f,0.f,0.f}, c1[4] = {0.f,0.f,0.f,0.f};
        #pragma unroll
        for (int ks = 0; ks < 4; ks++) {
            MMA(c0, af[0][ks], b0[ks], b1[ks]);
            MMA(c1, af[1][ks], b0[ks], b1[ks]);
        }
        const int k0i = nbase + tig * 2;
        const float Bc0 = sB[k0i], Bc1 = sB[k0i + 1];
        // scores (proxy = 2*dot - ||e||^2); gated inserts (gate skips only no-ops)
        {
            float sa = fmaf(2.f, c0[0], -Bc0), sb2 = fmaf(2.f, c0[1], -Bc1);
            if (fmaxf(sa, sb2) > TS[0][3]) { INS4(TS[0], TI[0], sa, k0i); INS4(TS[0], TI[0], sb2, k0i+1); }
        }
        {
            float sa = fmaf(2.f, c0[2], -Bc0), sb2 = fmaf(2.f, c0[3], -Bc1);
            if (fmaxf(sa, sb2) > TS[1][3]) { INS4(TS[1], TI[1], sa, k0i); INS4(TS[1], TI[1], sb2, k0i+1); }
        }
        {
            float sa = fmaf(2.f, c1[0], -Bc0), sb2 = fmaf(2.f, c1[1], -Bc1);
            if (fmaxf(sa, sb2) > TS[2][3]) { INS4(TS[2], TI[2], sa, k0i); INS4(TS[2], TI[2], sb2, k0i+1); }
        }
        {
            float sa = fmaf(2.f, c1[2], -Bc0), sb2 = fmaf(2.f, c1[3], -Bc1);
            if (fmaxf(sa, sb2) > TS[3][3]) { INS4(TS[3], TI[3], sa, k0i); INS4(TS[3], TI[3], sb2, k0i+1); }
        }
    }
    // quad merge (lanes in a quad own the same 4 rows, disjoint cols)
    #pragma unroll
    for (int dd = 1; dd <= 2; dd <<= 1) {
        #pragma unroll
        for (int j = 0; j < 4; j++) {
            float ns[4]; int ni[4];
            #pragma unroll
            for (int p = 0; p < 4; p++) {
                ns[p] = __shfl_xor_sync(0xffffffffu, TS[j][p], dd);
                ni[p] = __shfl_xor_sync(0xffffffffu, TI[j][p], dd);
            }
            #pragma unroll
            for (int p = 0; p < 4; p++) INS4(TS[j], TI[j], ns[p], ni[p]);
        }
    }
    // this thread owns row slot j == tig  (row = g + tig*8 within warp)
    const int rowp = rbase + g + tig * 8;
    const int n = n0 + rowp;
    float cs[4]; int ci[4];
    #pragma unroll
    for (int j = 0; j < 4; j++) if (tig == j) {
        #pragma unroll
        for (int p = 0; p < 4; p++) { cs[p] = TS[j][p]; ci[p] = TI[j][p]; }
    }
    const bool fb = (cs[3] >= cs[0] - MARGIN);
    CSWP(ci[0], ci[1]); CSWP(ci[2], ci[3]);
    CSWP(ci[0], ci[2]); CSWP(ci[1], ci[3]); CSWP(ci[1], ci[2]);

    // exact rescore (validated round-0 fl chain, ascending-k strict <)
    float xv[64];
    {
        const float4* xr = (const float4*)(xg + (size_t)n * D);
        #pragma unroll
        for (int j = 0; j < 16; j++) {
            float4 v = xr[j];
            xv[4*j] = v.x; xv[4*j+1] = v.y; xv[4*j+2] = v.z; xv[4*j+3] = v.w;
        }
    }
    float Av = 0.f;
    #pragma unroll
    for (int d = 0; d < D; d++) Av = fmaf(xv[d], xv[d], Av);
    float best = CUDART_INF_F; int bidx = 0;
    #pragma unroll
    for (int q = 0; q < 4; q++) {
        int idx = ci[q];
        const float4* er = (const float4*)(emb + (size_t)idx * D);
        float a = 0.f;
        #pragma unroll
        for (int j = 0; j < 16; j++) {
            float4 v = er[j];
            a = fmaf(xv[4*j],   v.x, a);
            a = fmaf(xv[4*j+1], v.y, a);
            a = fmaf(xv[4*j+2], v.z, a);
            a = fmaf(xv[4*j+3], v.w, a);
        }
        float ddv = (Av + sB[idx]) - 2.f * a;
        if (ddv < best) { best = ddv; bidx = idx; }
    }
    if (fb) { int sl = atomicAdd(&g_cnt, 1); g_list[sl] = n; }
    sIdx[rowp] = bidx;
    __syncthreads();

    // g_idx coalesced
    g_idx[n0 + tid] = sIdx[tid];

    // quantized_st + per-vector loss: LINEAR coalesced loop (L2-friendly)
    float ls = 0.f;
    {
        const float4* x4 = (const float4*)(xg + (size_t)n0 * D);
        float4* qo = (float4*)(out + (size_t)n0 * D);
        #pragma unroll
        for (int it = 0; it < 16; it++) {
            int i = tid + it * 512;
            int r = i >> 4, c4 = i & 15;
            int idx = sIdx[r];
            float4 xw = x4[i];
            float4 e4 = ((const float4*)(emb + (size_t)idx * D))[c4];
            float dx = e4.x - xw.x, dy = e4.y - xw.y;
            float dz = e4.z - xw.z, dw = e4.w - xw.w;
            float4 o4 = make_float4(xw.x + dx, xw.y + dy, xw.z + dz, xw.w + dw);
            __stcs(&qo[i], o4);
            ls += dx*dx + dy*dy + dz*dz + dw*dw;
        }
    }
    // block loss reduction: intra-warp shfl, then warp leaders
    #pragma unroll
    for (int o = 16; o; o >>= 1) ls += __shfl_down_sync(0xffffffffu, ls, o);
    if (lane == 0) sW[warp] = ls;
    __syncthreads();
    if (tid == 0) {
        float s = 0.f;
        #pragma unroll
        for (int w = 0; w < 16; w++) s += sW[w];
        g_part[blockIdx.x] = s;
    }
}

// ---------------- fallback: chunked-smem exact scan, 16 warps/block -------
// Patches g_idx / quantized_st / loss BEFORE vq_onehot (no one-hot rewrite).
#define FCHUNK 128
__global__ __launch_bounds__(512) void vq_fallback(
    const float* __restrict__ xg, const float* __restrict__ emb, float* __restrict__ out)
{
    __shared__ float sC[FCHUNK * 66];     // 33792B
    const int cnt = g_cnt;
    if (blockIdx.x * 16 >= cnt) return;   // whole block idle -> exit before syncs
    const int tid = threadIdx.x, warp = tid >> 5, lane = tid & 31;
    const int nwg = gridDim.x * 16;       // 256*16 = 4096 vectors per round
    const int rounds = (cnt + nwg - 1) / nwg;
    for (int rd = 0; rd < rounds; rd++) {
        const int it = rd * nwg + blockIdx.x * 16 + warp;
        const bool act = it < cnt;
        const int n = act ? g_list[it] : 0;
        float xv[64];
        float Av = 0.f;
        if (act) {
            const float4* xr = (const float4*)(xg + (size_t)n * D);
            #pragma unroll
            for (int j = 0; j < 16; j++) {
                float4 v = xr[j];
                xv[4*j] = v.x; xv[4*j+1] = v.y; xv[4*j+2] = v.z; xv[4*j+3] = v.w;
            }
            #pragma unroll
            for (int d = 0; d < D; d++) Av = fmaf(xv[d], xv[d], Av);
        }
        float best = CUDART_INF_F; int bidx = 0;
        for (int ch = 0; ch < K / FCHUNK; ch++) {
            __syncthreads();
            const float4* e4 = (const float4*)(emb + (size_t)ch * FCHUNK * D);
            for (int i = tid; i < FCHUNK * 16; i += 512) {
                float4 v = e4[i];
                int row = i >> 4, j = i & 15;
                float* p = sC + row * 66 + j * 4;
                ((float2*)p)[0] = make_float2(v.x, v.y);
                ((float2*)p)[1] = make_float2(v.z, v.w);
            }
            __syncthreads();
            if (act) {
                #pragma unroll
                for (int cj = 0; cj < FCHUNK / 32; cj++) {
                    int c = lane + cj * 32;
                    int k = ch * FCHUNK + c;
                    const float2* er = (const float2*)(sC + c * 66);
                    float a = 0.f;
                    #pragma unroll
                    for (int j = 0; j < 32; j++) {
                        float2 v = er[j];
                        a = fmaf(xv[2*j],   v.x, a);
                        a = fmaf(xv[2*j+1], v.y, a);
                    }
                    float ddv = (Av + g_B[k]) - 2.f * a;
                    if (ddv < best) { best = ddv; bidx = k; }
                }
            }
        }
        if (act) {
            // warp-min with lowest-k tie-break
            unsigned long long key =
                ((unsigned long long)__float_as_uint(best) << 32) | (unsigned)bidx;
            #pragma unroll
            for (int o = 16; o; o >>= 1) {
                unsigned long long k2 = __shfl_down_sync(0xffffffffu, key, o);
                if (k2 < key) key = k2;
            }
            key = __shfl_sync(0xffffffffu, key, 0);
            const int idx = (int)(key & 0xffffffffu);
            const int old = g_idx[n];
            if (idx != old) {
                if (lane == 0) g_idx[n] = idx;
                float lsn = 0.f, lso = 0.f;
                if (lane < 16) {
                    float4 e4 = ((const float4*)(emb + (size_t)idx * D))[lane];
                    float4 o4 = ((const float4*)(emb + (size_t)old * D))[lane];
                    float xx = xv[4*lane], xy = xv[4*lane+1], xz = xv[4*lane+2], xw2 = xv[4*lane+3];
                    float dx = e4.x-xx, dy = e4.y-xy, dz = e4.z-xz, dw = e4.w-xw2;
                    ((float4*)(out + (size_t)n * D))[lane] =
                        make_float4(xx+dx, xy+dy, xz+dz, xw2+dw);
                    lsn = dx*dx + dy*dy + dz*dz + dw*dw;
                    float ox = o4.x-xx, oy = o4.y-xy, oz = o4.z-xz, ow = o4.w-xw2;
                    lso = ox*ox + oy*oy + oz*oz + ow*ow;
                }
                #pragma unroll
                for (int o = 16; o; o >>= 1) {
                    lsn += __shfl_down_sync(0xffffffffu, lsn, o);
                    lso += __shfl_down_sync(0xffffffffu, lso, o);
                }
                if (lane == 0) atomicAdd(&g_fix, lsn - lso);
            }
        }
    }
}

// ---------------- one-hot encodings: dedicated streaming kernel -----------
__global__ __launch_bounds__(256) void vq_onehot(float* __restrict__ out) {
    __shared__ int sI[32];
    const int r0 = blockIdx.x * 32;       // grid 2048
    if (threadIdx.x < 32) sI[threadIdx.x] = g_idx[r0 + threadIdx.x];
    __syncthreads();
    float* eout = out + OUT_E_OFF;
    #pragma unroll 8
    for (int i = threadIdx.x; i < 32 * 256; i += 256) {
        int r = i >> 8, c4 = i & 255;
        int idx = sI[r];
        float4 v = make_float4(0.f, 0.f, 0.f, 0.f);
        if ((idx >> 2) == c4) ((float*)&v)[idx & 3] = 1.f;
        __stcs(&((float4*)(eout + (size_t)(r0 + r) * K))[c4], v);
    }
}

// ---------------- finalize: 128 partials + fix ----------------------------
__global__ void vq_finalize(float* __restrict__ out) {
    __shared__ double sR[128];
    int tid = threadIdx.x;   // 128
    sR[tid] = (double)g_part[tid];
    __syncthreads();
    #pragma unroll
    for (int st = 64; st; st >>= 1) {
        if (tid < st) sR[tid] += sR[tid + st];
        __syncthreads();
    }
    if (tid == 0) {
        double tot = sR[0] + (double)g_fix;
        float cb = (float)(tot / (double)((size_t)N_VEC * D));
        out[OUT_S_OFF + 0] = cb + 0.25f * cb;
        out[OUT_S_OFF + 1] = cb;
        out[OUT_S_OFF + 2] = cb;
    }
}

extern "C" void kernel_launch(void* const* d_in, const int* in_sizes, int n_in,
                              void* d_out, int out_size) {
    const float* x   = (const float*)d_in[0];
    const float* emb = (const float*)d_in[1];
    float* out = (float*)d_out;
    cudaFuncSetAttribute(vq_main, cudaFuncAttributeMaxDynamicSharedMemorySize, SMEM_TOTAL);
    vq_prep<<<8, 128>>>(emb);
    vq_main<<<NBLK, 512, SMEM_TOTAL>>>(x, emb, out);
    vq_fallback<<<256, 512>>>(x, emb, out);
    vq_onehot<<<N_VEC / 32, 256>>>(out);
    vq_finalize<<<1, 128>>>(out);
}

// round 10
// speedup vs baseline: 1.3817x; 1.0771x over previous
#include <cuda_runtime.h>
#include <cuda_fp16.h>
#include <cstdint>
#include <math_constants.h>

#define N_VEC 65536
#define D 64
#define K 1024
#define MTILE 512
#define NBLK (N_VEC / MTILE)       // 128
#define MARGIN 3e-5f
#define OUT_E_OFF ((size_t)N_VEC * D)
#define OUT_S_OFF (OUT_E_OFF + (size_t)N_VEC * K)

#define APAD 72                    // fp16 elems per padded row (144B)
#define BPAD 72
// M1 dynamic smem offsets (bytes)
#define OFF_SB  0                  // 4KB : g_B copy
#define OFF_A   4096               // 512*144 = 73728
#define OFF_B   77824              // 1024*144 = 147456
#define SMEM_TOTAL 225280

__device__ float  g_B[K];
__device__ __align__(16) __half g_ehf[K * BPAD];
__device__ int    g_cnt;
__device__ int    g_list[N_VEC];
__device__ int    g_idx[N_VEC];
__device__ __align__(16) int4 g_cand[N_VEC];
__device__ float  g_part2[512];
__device__ float  g_fix;

// descending top-4 insert (S[0] best). strict > keeps earlier (lower-k) on ties.
#define INS4(S, I, s, i) { if ((s) > S[3]) { \
    if ((s) > S[2]) { S[3]=S[2]; I[3]=I[2]; \
        if ((s) > S[1]) { S[2]=S[1]; I[2]=I[1]; \
            if ((s) > S[0]) { S[1]=S[0]; I[1]=I[0]; S[0]=(s); I[0]=(i); } \
            else { S[1]=(s); I[1]=(i); } } \
        else { S[2]=(s); I[2]=(i); } } \
    else { S[3]=(s); I[3]=(i); } } }

#define MMA(c, a, bb0, bb1) asm volatile( \
    "mma.sync.aligned.m16n8k16.row.col.f32.f16.f16.f32 " \
    "{%0,%1,%2,%3}, {%4,%5,%6,%7}, {%8,%9}, {%0,%1,%2,%3};" \
    : "+f"(c[0]), "+f"(c[1]), "+f"(c[2]), "+f"(c[3]) \
    : "r"(a[0]), "r"(a[1]), "r"(a[2]), "r"(a[3]), "r"(bb0), "r"(bb1))

#define CSWP(a, b) { if ((a) > (b)) { int _t = (a); (a) = (b); (b) = _t; } }

// ---------------- prep: g_B (exact chain) + padded fp16 codebook ----------
__global__ void vq_prep(const float* __restrict__ emb) {
    int k = blockIdx.x * blockDim.x + threadIdx.x;    // 8 x 128 = 1024
    float v[D];
    const float4* r4 = (const float4*)(emb + (size_t)k * D);
    #pragma unroll
    for (int j = 0; j < 16; j++) {
        float4 t = r4[j];
        v[4*j] = t.x; v[4*j+1] = t.y; v[4*j+2] = t.z; v[4*j+3] = t.w;
    }
    float bb = 0.f;
    #pragma unroll
    for (int d = 0; d < D; d++) bb += v[d] * v[d];
    g_B[k] = bb;
    __half2* eb = (__half2*)(g_ehf + (size_t)k * BPAD);
    #pragma unroll
    for (int j = 0; j < 32; j++)
        eb[j] = __floats2half2_rn(v[2*j], v[2*j+1]);
    #pragma unroll
    for (int j = 32; j < 36; j++)
        eb[j] = __floats2half2_rn(0.f, 0.f);
    if (k == 0) { g_cnt = 0; g_fix = 0.f; }
}

// ---------------- M1: HMMA(fp16) prefilter + top4 candidates only ---------
__global__ __launch_bounds__(512, 1) void vq_m1(
    const float* __restrict__ xg)
{
    extern __shared__ char sm[];
    float*    sB = (float*)(sm + OFF_SB);
    uint32_t* Aw = (uint32_t*)(sm + OFF_A);   // 36 words per padded row
    uint32_t* Bw = (uint32_t*)(sm + OFF_B);

    const int tid = threadIdx.x;
    const int warp = tid >> 5, lane = tid & 31;
    const int g = lane >> 2, tig = lane & 3;
    const int n0 = blockIdx.x * MTILE;

    for (int i = tid; i < K; i += 512) sB[i] = g_B[i];
    { // stage A: x f32 -> fp16 padded rows
        const float4* x4 = (const float4*)(xg + (size_t)n0 * D);
        for (int i = tid; i < MTILE * 16; i += 512) {
            float4 v = x4[i];
            int row = i >> 4, j = i & 15;
            __half2* p = (__half2*)((__half*)(sm + OFF_A) + row * APAD + j * 4);
            p[0] = __floats2half2_rn(v.x, v.y);
            p[1] = __floats2half2_rn(v.z, v.w);
        }
    }
    { // stage B: padded fp16 codebook copy
        const float4* e4 = (const float4*)g_ehf;
        float4* s4 = (float4*)(sm + OFF_B);
        for (int i = tid; i < (K * BPAD * 2) / 16; i += 512) s4[i] = e4[i];
    }
    __syncthreads();

    const int rbase = warp * 32;
    // preload A fragments: [rowtile][kstep][4 regs]
    uint32_t af[2][4][4];
    #pragma unroll
    for (int rt = 0; rt < 2; rt++) {
        int r0w = (rbase + rt * 16 + g) * 36;
        #pragma unroll
        for (int ks = 0; ks < 4; ks++) {
            int kw = ks * 8 + tig;
            af[rt][ks][0] = Aw[r0w + kw];
            af[rt][ks][1] = Aw[r0w + 288 + kw];      // +8 rows
            af[rt][ks][2] = Aw[r0w + kw + 4];
            af[rt][ks][3] = Aw[r0w + 288 + kw + 4];
        }
    }
    float TS[4][4]; int TI[4][4];
    #pragma unroll
    for (int j = 0; j < 4; j++)
        #pragma unroll
        for (int p = 0; p < 4; p++) { TS[j][p] = -CUDART_INF_F; TI[j][p] = 0; }

    for (int nt = 0; nt < 128; nt++) {
        const int nbase = nt * 8;
        uint32_t b0[4], b1[4];
        const int brw = (nbase + g) * 36;
        #pragma unroll
        for (int ks = 0; ks < 4; ks++) {
            b0[ks] = Bw[brw + ks * 8 + tig];
            b1[ks] = Bw[brw + ks * 8 + tig + 4];
        }
        float c0[4] = {0.f,0.f,0.f,0.f}, c1[4] = {0.f,0.f,0.f,0.f};
        #pragma unroll
        for (int ks = 0; ks < 4; ks++) {
            MMA(c0, af[0][ks], b0[ks], b1[ks]);
            MMA(c1, af[1][ks], b0[ks], b1[ks]);
        }
        const int k0i = nbase + tig * 2;
        const float Bc0 = sB[k0i], Bc1 = sB[k0i + 1];
        // scores (proxy = 2*dot - ||e||^2); gated inserts (gate skips only no-ops)
        {
            float sa = fmaf(2.f, c0[0], -Bc0), sb2 = fmaf(2.f, c0[1], -Bc1);
            if (fmaxf(sa, sb2) > TS[0][3]) { INS4(TS[0], TI[0], sa, k0i); INS4(TS[0], TI[0], sb2, k0i+1); }
        }
        {
            float sa = fmaf(2.f, c0[2], -Bc0), sb2 = fmaf(2.f, c0[3], -Bc1);
            if (fmaxf(sa, sb2) > TS[1][3]) { INS4(TS[1], TI[1], sa, k0i); INS4(TS[1], TI[1], sb2, k0i+1); }
        }
        {
            float sa = fmaf(2.f, c1[0], -Bc0), sb2 = fmaf(2.f, c1[1], -Bc1);
            if (fmaxf(sa, sb2) > TS[2][3]) { INS4(TS[2], TI[2], sa, k0i); INS4(TS[2], TI[2], sb2, k0i+1); }
        }
        {
            float sa = fmaf(2.f, c1[2], -Bc0), sb2 = fmaf(2.f, c1[3], -Bc1);
            if (fmaxf(sa, sb2) > TS[3][3]) { INS4(TS[3], TI[3], sa, k0i); INS4(TS[3], TI[3], sb2, k0i+1); }
        }
    }
    // quad merge (lanes in a quad own the same 4 rows, disjoint cols)
    #pragma unroll
    for (int dd = 1; dd <= 2; dd <<= 1) {
        #pragma unroll
        for (int j = 0; j < 4; j++) {
            float ns[4]; int ni[4];
            #pragma unroll
            for (int p = 0; p < 4; p++) {
                ns[p] = __shfl_xor_sync(0xffffffffu, TS[j][p], dd);
                ni[p] = __shfl_xor_sync(0xffffffffu, TI[j][p], dd);
            }
            #pragma unroll
            for (int p = 0; p < 4; p++) INS4(TS[j], TI[j], ns[p], ni[p]);
        }
    }
    // this thread owns row slot j == tig  (row = g + tig*8 within warp)
    const int rowp = rbase + g + tig * 8;
    const int n = n0 + rowp;
    float cs[4]; int ci[4];
    #pragma unroll
    for (int j = 0; j < 4; j++) if (tig == j) {
        #pragma unroll
        for (int p = 0; p < 4; p++) { cs[p] = TS[j][p]; ci[p] = TI[j][p]; }
    }
    const bool fb = (cs[3] >= cs[0] - MARGIN);
    CSWP(ci[0], ci[1]); CSWP(ci[2], ci[3]);
    CSWP(ci[0], ci[2]); CSWP(ci[1], ci[3]); CSWP(ci[1], ci[2]);
    if (fb) { int sl = atomicAdd(&g_cnt, 1); g_list[sl] = n; }
    g_cand[n] = make_int4(ci[0], ci[1], ci[2], ci[3]);
}

// ---------------- M2: exact rescore + quantized_st + loss (high occ) ------
__global__ __launch_bounds__(128) void vq_m2(
    const float* __restrict__ xg, const float* __restrict__ emb, float* __restrict__ out)
{
    __shared__ int   sIdx[128];
    __shared__ float sW[4];
    const int tid = threadIdx.x, lane = tid & 31, warp = tid >> 5;
    const int n0 = blockIdx.x * 128;
    const int n = n0 + tid;

    int4 cd = g_cand[n];
    float xv[64];
    {
        const float4* xr = (const float4*)(xg + (size_t)n * D);
        #pragma unroll
        for (int j = 0; j < 16; j++) {
            float4 v = xr[j];
            xv[4*j] = v.x; xv[4*j+1] = v.y; xv[4*j+2] = v.z; xv[4*j+3] = v.w;
        }
    }
    float Av = 0.f;
    #pragma unroll
    for (int d = 0; d < D; d++) Av = fmaf(xv[d], xv[d], Av);

    int cand[4] = {cd.x, cd.y, cd.z, cd.w};
    float best = CUDART_INF_F; int bidx = 0;
    #pragma unroll
    for (int q = 0; q < 4; q++) {
        int idx = cand[q];
        const float4* er = (const float4*)(emb + (size_t)idx * D);
        float a = 0.f;
        #pragma unroll
        for (int j = 0; j < 16; j++) {
            float4 v = er[j];
            a = fmaf(xv[4*j],   v.x, a);
            a = fmaf(xv[4*j+1], v.y, a);
            a = fmaf(xv[4*j+2], v.z, a);
            a = fmaf(xv[4*j+3], v.w, a);
        }
        float ddv = (Av + g_B[idx]) - 2.f * a;
        if (ddv < best) { best = ddv; bidx = idx; }   // ascending k, strict <
    }
    sIdx[tid] = bidx;
    g_idx[n] = bidx;
    __syncthreads();

    // quantized_st + loss: linear coalesced loop over the 128-vector tile
    float ls = 0.f;
    {
        const float4* x4 = (const float4*)(xg + (size_t)n0 * D);
        float4* qo = (float4*)(out + (size_t)n0 * D);
        #pragma unroll
        for (int it = 0; it < 16; it++) {
            int i = tid + it * 128;
            int r = i >> 4, c4 = i & 15;
            int idx = sIdx[r];
            float4 xw = x4[i];
            float4 e4 = ((const float4*)(emb + (size_t)idx * D))[c4];
            float dx = e4.x - xw.x, dy = e4.y - xw.y;
            float dz = e4.z - xw.z, dw = e4.w - xw.w;
            __stcs(&qo[i], make_float4(xw.x + dx, xw.y + dy, xw.z + dz, xw.w + dw));
            ls += dx*dx + dy*dy + dz*dz + dw*dw;
        }
    }
    #pragma unroll
    for (int o = 16; o; o >>= 1) ls += __shfl_down_sync(0xffffffffu, ls, o);
    if (lane == 0) sW[warp] = ls;
    __syncthreads();
    if (tid == 0) g_part2[blockIdx.x] = sW[0] + sW[1] + sW[2] + sW[3];
}

// ---------------- fallback: chunked-smem exact scan, 16 warps/block -------
#define FCHUNK 128
__global__ __launch_bounds__(512) void vq_fallback(
    const float* __restrict__ xg, const float* __restrict__ emb, float* __restrict__ out)
{
    __shared__ float sC[FCHUNK * 66];     // 33792B
    const int cnt = g_cnt;
    if (blockIdx.x * 16 >= cnt) return;
    const int tid = threadIdx.x, warp = tid >> 5, lane = tid & 31;
    const int nwg = gridDim.x * 16;       // 4096 vectors per round
    const int rounds = (cnt + nwg - 1) / nwg;
    for (int rd = 0; rd < rounds; rd++) {
        const int it = rd * nwg + blockIdx.x * 16 + warp;
        const bool act = it < cnt;
        const int n = act ? g_list[it] : 0;
        float xv[64];
        float Av = 0.f;
        if (act) {
            const float4* xr = (const float4*)(xg + (size_t)n * D);
            #pragma unroll
            for (int j = 0; j < 16; j++) {
                float4 v = xr[j];
                xv[4*j] = v.x; xv[4*j+1] = v.y; xv[4*j+2] = v.z; xv[4*j+3] = v.w;
            }
            #pragma unroll
            for (int d = 0; d < D; d++) Av = fmaf(xv[d], xv[d], Av);
        }
        float best = CUDART_INF_F; int bidx = 0;
        for (int ch = 0; ch < K / FCHUNK; ch++) {
            __syncthreads();
            const float4* e4 = (const float4*)(emb + (size_t)ch * FCHUNK * D);
            for (int i = tid; i < FCHUNK * 16; i += 512) {
                float4 v = e4[i];
                int row = i >> 4, j = i & 15;
                float* p = sC + row * 66 + j * 4;
                ((float2*)p)[0] = make_float2(v.x, v.y);
                ((float2*)p)[1] = make_float2(v.z, v.w);
            }
            __syncthreads();
            if (act) {
                #pragma unroll
                for (int cj = 0; cj < FCHUNK / 32; cj++) {
                    int c = lane + cj * 32;
                    int k = ch * FCHUNK + c;
                    const float2* er = (const float2*)(sC + c * 66);
                    float a = 0.f;
                    #pragma unroll
                    for (int j = 0; j < 32; j++) {
                        float2 v = er[j];
                        a = fmaf(xv[2*j],   v.x, a);
                        a = fmaf(xv[2*j+1], v.y, a);
                    }
                    float ddv = (Av + g_B[k]) - 2.f * a;
                    if (ddv < best) { best = ddv; bidx = k; }
                }
            }
        }
        if (act) {
            unsigned long long key =
                ((unsigned long long)__float_as_uint(best) << 32) | (unsigned)bidx;
            #pragma unroll
            for (int o = 16; o; o >>= 1) {
                unsigned long long k2 = __shfl_down_sync(0xffffffffu, key, o);
                if (k2 < key) key = k2;
            }
            key = __shfl_sync(0xffffffffu, key, 0);
            const int idx = (int)(key & 0xffffffffu);
            const int old = g_idx[n];
            if (idx != old) {
                if (lane == 0) g_idx[n] = idx;
                float lsn = 0.f, lso = 0.f;
                if (lane < 16) {
                    float4 e4 = ((const float4*)(emb + (size_t)idx * D))[lane];
                    float4 o4 = ((const float4*)(emb + (size_t)old * D))[lane];
                    float xx = xv[4*lane], xy = xv[4*lane+1], xz = xv[4*lane+2], xw2 = xv[4*lane+3];
                    float dx = e4.x-xx, dy = e4.y-xy, dz = e4.z-xz, dw = e4.w-xw2;
                    ((float4*)(out + (size_t)n * D))[lane] =
                        make_float4(xx+dx, xy+dy, xz+dz, xw2+dw);
                    lsn = dx*dx + dy*dy + dz*dz + dw*dw;
                    float ox = o4.x-xx, oy = o4.y-xy, oz = o4.z-xz, ow = o4.w-xw2;
                    lso = ox*ox + oy*oy + oz*oz + ow*ow;
                }
                #pragma unroll
                for (int o = 16; o; o >>= 1) {
                    lsn += __shfl_down_sync(0xffffffffu, lsn, o);
                    lso += __shfl_down_sync(0xffffffffu, lso, o);
                }
                if (lane == 0) atomicAdd(&g_fix, lsn - lso);
            }
        }
    }
}

// ---------------- one-hot encodings: dedicated streaming kernel -----------
__global__ __launch_bounds__(256) void vq_onehot(float* __restrict__ out) {
    __shared__ int sI[32];
    const int r0 = blockIdx.x * 32;       // grid 2048
    if (threadIdx.x < 32) sI[threadIdx.x] = g_idx[r0 + threadIdx.x];
    __syncthreads();
    float* eout = out + OUT_E_OFF;
    #pragma unroll 8
    for (int i = threadIdx.x; i < 32 * 256; i += 256) {
        int r = i >> 8, c4 = i & 255;
        int idx = sI[r];
        float4 v = make_float4(0.f, 0.f, 0.f, 0.f);
        if ((idx >> 2) == c4) ((float*)&v)[idx & 3] = 1.f;
        __stcs(&((float4*)(eout + (size_t)(r0 + r) * K))[c4], v);
    }
}

// ---------------- finalize: 512 partials + fix ----------------------------
__global__ void vq_finalize(float* __restrict__ out) {
    __shared__ double sR[256];
    int tid = threadIdx.x;   // 256
    sR[tid] = (double)g_part2[tid] + (double)g_part2[tid + 256];
    __syncthreads();
    #pragma unroll
    for (int st = 128; st; st >>= 1) {
        if (tid < st) sR[tid] += sR[tid + st];
        __syncthreads();
    }
    if (tid == 0) {
        double tot = sR[0] + (double)g_fix;
        float cb = (float)(tot / (double)((size_t)N_VEC * D));
        out[OUT_S_OFF + 0] = cb + 0.25f * cb;
        out[OUT_S_OFF + 1] = cb;
        out[OUT_S_OFF + 2] = cb;
    }
}

extern "C" void kernel_launch(void* const* d_in, const int* in_sizes, int n_in,
                              void* d_out, int out_size) {
    const float* x   = (const float*)d_in[0];
    const float* emb = (const float*)d_in[1];
    float* out = (float*)d_out;
    cudaFuncSetAttribute(vq_m1, cudaFuncAttributeMaxDynamicSharedMemorySize, SMEM_TOTAL);
    vq_prep<<<8, 128>>>(emb);
    vq_m1<<<NBLK, 512, SMEM_TOTAL>>>(x);
    vq_m2<<<512, 128>>>(x, emb, out);
    vq_fallback<<<256, 512>>>(x, emb, out);
    vq_onehot<<<N_VEC / 32, 256>>>(out);
    vq_finalize<<<1, 256>>>(out);
}

// round 11
// speedup vs baseline: 1.6824x; 1.2176x over previous
#include <cuda_runtime.h>
#include <cuda_fp16.h>
#include <cstdint>
#include <math_constants.h>

#define N_VEC 65536
#define D 64
#define K 1024
#define MTILE 512
#define NBLK (N_VEC / MTILE)       // 128
#define MARGIN 5e-5f
#define OUT_E_OFF ((size_t)N_VEC * D)
#define OUT_S_OFF (OUT_E_OFF + (size_t)N_VEC * K)

#define APAD 72                    // fp16 elems per padded row (144B)
#define BPAD 72
// M1 dynamic smem offsets (bytes)
#define OFF_SB  0                  // 4KB : g_B copy
#define OFF_A   4096               // 512*144 = 73728
#define OFF_B   77824              // 1024*144 = 147456
#define SMEM_TOTAL 225280

__device__ float  g_B[K];
__device__ __align__(16) __half g_ehf[K * BPAD];
__device__ int    g_cnt;
__device__ int    g_list[N_VEC];
__device__ int    g_idx[N_VEC];
__device__ __align__(16) int4 g_cand[N_VEC];
__device__ float  g_part2[512];
__device__ float  g_fix;

// ---- packed orderable key: [31:10] quantized score (orderable-int), [9:0] 1023-k
__device__ __forceinline__ uint32_t packkey(float s, uint32_t kinv) {
    uint32_t b = __float_as_uint(s);
    uint32_t m = (uint32_t)((int)b >> 31) | 0x80000000u;
    return ((b ^ m) & 0xFFFFFC00u) | kinv;
}
__device__ __forceinline__ float unpackkey(uint32_t key) {
    uint32_t ko = key & 0xFFFFFC00u;
    uint32_t m = (ko & 0x80000000u) ? 0x80000000u : 0xFFFFFFFFu;
    return __uint_as_float(ko ^ m);
}
// branchless insert into descending top-4 (7 IMNMX)
#define INSK(S, t0) { uint32_t _t = (t0), _u; \
    _u = max((S)[0], _t); _t = min((S)[0], _t); (S)[0] = _u; \
    _u = max((S)[1], _t); _t = min((S)[1], _t); (S)[1] = _u; \
    _u = max((S)[2], _t); _t = min((S)[2], _t); (S)[2] = _u; \
    (S)[3] = max((S)[3], _t); }

#define MMA(c, a, bb0, bb1) asm volatile( \
    "mma.sync.aligned.m16n8k16.row.col.f32.f16.f16.f32 " \
    "{%0,%1,%2,%3}, {%4,%5,%6,%7}, {%8,%9}, {%0,%1,%2,%3};" \
    : "+f"(c[0]), "+f"(c[1]), "+f"(c[2]), "+f"(c[3]) \
    : "r"(a[0]), "r"(a[1]), "r"(a[2]), "r"(a[3]), "r"(bb0), "r"(bb1))

#define CSWP(a, b) { if ((a) > (b)) { int _t = (a); (a) = (b); (b) = _t; } }

// ---------------- prep: g_B (exact chain) + padded fp16 codebook ----------
__global__ void vq_prep(const float* __restrict__ emb) {
    int k = blockIdx.x * blockDim.x + threadIdx.x;    // 8 x 128 = 1024
    float v[D];
    const float4* r4 = (const float4*)(emb + (size_t)k * D);
    #pragma unroll
    for (int j = 0; j < 16; j++) {
        float4 t = r4[j];
        v[4*j] = t.x; v[4*j+1] = t.y; v[4*j+2] = t.z; v[4*j+3] = t.w;
    }
    float bb = 0.f;
    #pragma unroll
    for (int d = 0; d < D; d++) bb += v[d] * v[d];
    g_B[k] = bb;
    __half2* eb = (__half2*)(g_ehf + (size_t)k * BPAD);
    #pragma unroll
    for (int j = 0; j < 32; j++)
        eb[j] = __floats2half2_rn(v[2*j], v[2*j+1]);
    #pragma unroll
    for (int j = 32; j < 36; j++)
        eb[j] = __floats2half2_rn(0.f, 0.f);
    if (k == 0) { g_cnt = 0; g_fix = 0.f; }
}

// ---------------- M1: HMMA(fp16) prefilter + branchless packed top-4 ------
__global__ __launch_bounds__(512, 1) void vq_m1(
    const float* __restrict__ xg)
{
    extern __shared__ char sm[];
    float*    sB = (float*)(sm + OFF_SB);
    uint32_t* Aw = (uint32_t*)(sm + OFF_A);   // 36 words per padded row
    uint32_t* Bw = (uint32_t*)(sm + OFF_B);

    const int tid = threadIdx.x;
    const int warp = tid >> 5, lane = tid & 31;
    const int g = lane >> 2, tig = lane & 3;
    const int n0 = blockIdx.x * MTILE;

    for (int i = tid; i < K; i += 512) sB[i] = g_B[i];
    { // stage A: x f32 -> fp16 padded rows
        const float4* x4 = (const float4*)(xg + (size_t)n0 * D);
        for (int i = tid; i < MTILE * 16; i += 512) {
            float4 v = x4[i];
            int row = i >> 4, j = i & 15;
            __half2* p = (__half2*)((__half*)(sm + OFF_A) + row * APAD + j * 4);
            p[0] = __floats2half2_rn(v.x, v.y);
            p[1] = __floats2half2_rn(v.z, v.w);
        }
    }
    { // stage B: padded fp16 codebook copy
        const float4* e4 = (const float4*)g_ehf;
        float4* s4 = (float4*)(sm + OFF_B);
        for (int i = tid; i < (K * BPAD * 2) / 16; i += 512) s4[i] = e4[i];
    }
    __syncthreads();

    const int rbase = warp * 32;
    // preload A fragments: [rowtile][kstep][4 regs]
    uint32_t af[2][4][4];
    #pragma unroll
    for (int rt = 0; rt < 2; rt++) {
        int r0w = (rbase + rt * 16 + g) * 36;
        #pragma unroll
        for (int ks = 0; ks < 4; ks++) {
            int kw = ks * 8 + tig;
            af[rt][ks][0] = Aw[r0w + kw];
            af[rt][ks][1] = Aw[r0w + 288 + kw];      // +8 rows
            af[rt][ks][2] = Aw[r0w + kw + 4];
            af[rt][ks][3] = Aw[r0w + 288 + kw + 4];
        }
    }
    uint32_t S[4][4];
    #pragma unroll
    for (int j = 0; j < 4; j++)
        #pragma unroll
        for (int p = 0; p < 4; p++) S[j][p] = 0u;

    for (int nt = 0; nt < 128; nt++) {
        const int nbase = nt * 8;
        uint32_t b0[4], b1[4];
        const int brw = (nbase + g) * 36;
        #pragma unroll
        for (int ks = 0; ks < 4; ks++) {
            b0[ks] = Bw[brw + ks * 8 + tig];
            b1[ks] = Bw[brw + ks * 8 + tig + 4];
        }
        float c0[4] = {0.f,0.f,0.f,0.f}, c1[4] = {0.f,0.f,0.f,0.f};
        #pragma unroll
        for (int ks = 0; ks < 4; ks++) {
            MMA(c0, af[0][ks], b0[ks], b1[ks]);
            MMA(c1, af[1][ks], b0[ks], b1[ks]);
        }
        const int k0i = nbase + tig * 2;
        const float Bc0 = sB[k0i], Bc1 = sB[k0i + 1];
        const uint32_t kv0 = 1023u - (uint32_t)k0i;
        const uint32_t kv1 = 1022u - (uint32_t)k0i;
        // branchless: pack (score, k) -> orderable key, bubble into top-4
        INSK(S[0], packkey(fmaf(2.f, c0[0], -Bc0), kv0));
        INSK(S[0], packkey(fmaf(2.f, c0[1], -Bc1), kv1));
        INSK(S[1], packkey(fmaf(2.f, c0[2], -Bc0), kv0));
        INSK(S[1], packkey(fmaf(2.f, c0[3], -Bc1), kv1));
        INSK(S[2], packkey(fmaf(2.f, c1[0], -Bc0), kv0));
        INSK(S[2], packkey(fmaf(2.f, c1[1], -Bc1), kv1));
        INSK(S[3], packkey(fmaf(2.f, c1[2], -Bc0), kv0));
        INSK(S[3], packkey(fmaf(2.f, c1[3], -Bc1), kv1));
    }
    // quad merge (lanes in a quad own the same 4 rows, disjoint cols)
    #pragma unroll
    for (int dd = 1; dd <= 2; dd <<= 1) {
        #pragma unroll
        for (int j = 0; j < 4; j++) {
            uint32_t ns[4];
            #pragma unroll
            for (int p = 0; p < 4; p++)
                ns[p] = __shfl_xor_sync(0xffffffffu, S[j][p], dd);
            #pragma unroll
            for (int p = 0; p < 4; p++) INSK(S[j], ns[p]);
        }
    }
    // this thread owns row slot j == tig  (row = g + tig*8 within warp)
    const int rowp = rbase + g + tig * 8;
    const int n = n0 + rowp;
    uint32_t K0 = 0, K1 = 0, K2 = 0, K3 = 0;
    #pragma unroll
    for (int j = 0; j < 4; j++) if (tig == j) {
        K0 = S[j][0]; K1 = S[j][1]; K2 = S[j][2]; K3 = S[j][3];
    }
    const float s0f = unpackkey(K0), s3f = unpackkey(K3);
    const bool fb = (s3f >= s0f - MARGIN);
    int ci[4] = { 1023 - (int)(K0 & 1023u), 1023 - (int)(K1 & 1023u),
                  1023 - (int)(K2 & 1023u), 1023 - (int)(K3 & 1023u) };
    CSWP(ci[0], ci[1]); CSWP(ci[2], ci[3]);
    CSWP(ci[0], ci[2]); CSWP(ci[1], ci[3]); CSWP(ci[1], ci[2]);
    if (fb) { int sl = atomicAdd(&g_cnt, 1); g_list[sl] = n; }
    g_cand[n] = make_int4(ci[0], ci[1], ci[2], ci[3]);
}

// ---------------- M2: exact rescore + quantized_st + loss (high occ) ------
__global__ __launch_bounds__(128) void vq_m2(
    const float* __restrict__ xg, const float* __restrict__ emb, float* __restrict__ out)
{
    __shared__ int   sIdx[128];
    __shared__ float sW[4];
    const int tid = threadIdx.x, lane = tid & 31, warp = tid >> 5;
    const int n0 = blockIdx.x * 128;
    const int n = n0 + tid;

    int4 cd = g_cand[n];
    float xv[64];
    {
        const float4* xr = (const float4*)(xg + (size_t)n * D);
        #pragma unroll
        for (int j = 0; j < 16; j++) {
            float4 v = xr[j];
            xv[4*j] = v.x; xv[4*j+1] = v.y; xv[4*j+2] = v.z; xv[4*j+3] = v.w;
        }
    }
    float Av = 0.f;
    #pragma unroll
    for (int d = 0; d < D; d++) Av = fmaf(xv[d], xv[d], Av);

    int cand[4] = {cd.x, cd.y, cd.z, cd.w};
    float best = CUDART_INF_F; int bidx = 0;
    #pragma unroll
    for (int q = 0; q < 4; q++) {
        int idx = cand[q];
        const float4* er = (const float4*)(emb + (size_t)idx * D);
        float a = 0.f;
        #pragma unroll
        for (int j = 0; j < 16; j++) {
            float4 v = er[j];
            a = fmaf(xv[4*j],   v.x, a);
            a = fmaf(xv[4*j+1], v.y, a);
            a = fmaf(xv[4*j+2], v.z, a);
            a = fmaf(xv[4*j+3], v.w, a);
        }
        float ddv = (Av + g_B[idx]) - 2.f * a;
        if (ddv < best) { best = ddv; bidx = idx; }   // ascending k, strict <
    }
    sIdx[tid] = bidx;
    g_idx[n] = bidx;
    __syncthreads();

    // quantized_st + loss: linear coalesced loop over the 128-vector tile
    float ls = 0.f;
    {
        const float4* x4 = (const float4*)(xg + (size_t)n0 * D);
        float4* qo = (float4*)(out + (size_t)n0 * D);
        #pragma unroll
        for (int it = 0; it < 16; it++) {
            int i = tid + it * 128;
            int r = i >> 4, c4 = i & 15;
            int idx = sIdx[r];
            float4 xw = x4[i];
            float4 e4 = ((const float4*)(emb + (size_t)idx * D))[c4];
            float dx = e4.x - xw.x, dy = e4.y - xw.y;
            float dz = e4.z - xw.z, dw = e4.w - xw.w;
            __stcs(&qo[i], make_float4(xw.x + dx, xw.y + dy, xw.z + dz, xw.w + dw));
            ls += dx*dx + dy*dy + dz*dz + dw*dw;
        }
    }
    #pragma unroll
    for (int o = 16; o; o >>= 1) ls += __shfl_down_sync(0xffffffffu, ls, o);
    if (lane == 0) sW[warp] = ls;
    __syncthreads();
    if (tid == 0) g_part2[blockIdx.x] = sW[0] + sW[1] + sW[2] + sW[3];
}

// ---------------- fallback: chunked-smem, 2 vectors/warp, 1 wave ----------
#define FCHUNK 128
#define FBLOCKS 148
#define VPB 16                      // 8 warps x 2 vectors
__global__ __launch_bounds__(256) void vq_fallback(
    const float* __restrict__ xg, const float* __restrict__ emb, float* __restrict__ out)
{
    __shared__ float sC[FCHUNK * 66];     // 33792B
    const int cnt = g_cnt;
    if (blockIdx.x * VPB >= cnt) return;
    const int tid = threadIdx.x, warp = tid >> 5, lane = tid & 31;
    const int nwg = FBLOCKS * VPB;        // 2368 vectors per round
    const int rounds = (cnt + nwg - 1) / nwg;
    for (int rd = 0; rd < rounds; rd++) {
        const int base = rd * nwg + blockIdx.x * VPB + warp * 2;
        if (rd * nwg + blockIdx.x * VPB >= cnt) break;
        const bool a0 = base < cnt, a1 = base + 1 < cnt;
        const int nA = a0 ? g_list[base] : 0;
        const int nB = a1 ? g_list[base + 1] : 0;
        float xv0[64], xv1[64];
        float Av0 = 0.f, Av1 = 0.f;
        if (a0) {
            const float4* xr = (const float4*)(xg + (size_t)nA * D);
            #pragma unroll
            for (int j = 0; j < 16; j++) {
                float4 v = xr[j];
                xv0[4*j] = v.x; xv0[4*j+1] = v.y; xv0[4*j+2] = v.z; xv0[4*j+3] = v.w;
            }
            #pragma unroll
            for (int d = 0; d < D; d++) Av0 = fmaf(xv0[d], xv0[d], Av0);
        }
        if (a1) {
            const float4* xr = (const float4*)(xg + (size_t)nB * D);
            #pragma unroll
            for (int j = 0; j < 16; j++) {
                float4 v = xr[j];
                xv1[4*j] = v.x; xv1[4*j+1] = v.y; xv1[4*j+2] = v.z; xv1[4*j+3] = v.w;
            }
            #pragma unroll
            for (int d = 0; d < D; d++) Av1 = fmaf(xv1[d], xv1[d], Av1);
        }
        float best0 = CUDART_INF_F, best1 = CUDART_INF_F;
        int bidx0 = 0, bidx1 = 0;
        for (int ch = 0; ch < K / FCHUNK; ch++) {
            __syncthreads();
            const float4* e4 = (const float4*)(emb + (size_t)ch * FCHUNK * D);
            for (int i = tid; i < FCHUNK * 16; i += 256) {
                float4 v = e4[i];
                int row = i >> 4, j = i & 15;
                float* p = sC + row * 66 + j * 4;
                ((float2*)p)[0] = make_float2(v.x, v.y);
                ((float2*)p)[1] = make_float2(v.z, v.w);
            }
            __syncthreads();
            if (a0) {
                #pragma unroll
                for (int cj = 0; cj < FCHUNK / 32; cj++) {
                    int c = lane + cj * 32;
                    int k = ch * FCHUNK + c;
                    const float2* er = (const float2*)(sC + c * 66);
                    float aa = 0.f, ab = 0.f;
                    #pragma unroll
                    for (int j = 0; j < 32; j++) {
                        float2 v = er[j];
                        aa = fmaf(xv0[2*j],   v.x, aa);
                        aa = fmaf(xv0[2*j+1], v.y, aa);
                        if (a1) {
                            ab = fmaf(xv1[2*j],   v.x, ab);
                            ab = fmaf(xv1[2*j+1], v.y, ab);
                        }
                    }
                    float d0 = (Av0 + g_B[k]) - 2.f * aa;
                    if (d0 < best0) { best0 = d0; bidx0 = k; }
                    if (a1) {
                        float d1 = (Av1 + g_B[k]) - 2.f * ab;
                        if (d1 < best1) { best1 = d1; bidx1 = k; }
                    }
                }
            }
        }
        // patch vector A
        if (a0) {
            unsigned long long key =
                ((unsigned long long)__float_as_uint(best0) << 32) | (unsigned)bidx0;
            #pragma unroll
            for (int o = 16; o; o >>= 1) {
                unsigned long long k2 = __shfl_down_sync(0xffffffffu, key, o);
                if (k2 < key) key = k2;
            }
            key = __shfl_sync(0xffffffffu, key, 0);
            const int idx = (int)(key & 0xffffffffu);
            const int old = g_idx[nA];
            if (idx != old) {
                if (lane == 0) g_idx[nA] = idx;
                float lsn = 0.f, lso = 0.f;
                if (lane < 16) {
                    float4 e4 = ((const float4*)(emb + (size_t)idx * D))[lane];
                    float4 o4 = ((const float4*)(emb + (size_t)old * D))[lane];
                    float xx = xv0[4*lane], xy = xv0[4*lane+1], xz = xv0[4*lane+2], xw2 = xv0[4*lane+3];
                    float dx = e4.x-xx, dy = e4.y-xy, dz = e4.z-xz, dw = e4.w-xw2;
                    ((float4*)(out + (size_t)nA * D))[lane] =
                        make_float4(xx+dx, xy+dy, xz+dz, xw2+dw);
                    lsn = dx*dx + dy*dy + dz*dz + dw*dw;
                    float ox = o4.x-xx, oy = o4.y-xy, oz = o4.z-xz, ow = o4.w-xw2;
                    lso = ox*ox + oy*oy + oz*oz + ow*ow;
                }
                #pragma unroll
                for (int o = 16; o; o >>= 1) {
                    lsn += __shfl_down_sync(0xffffffffu, lsn, o);
                    lso += __shfl_down_sync(0xffffffffu, lso, o);
                }
                if (lane == 0) atomicAdd(&g_fix, lsn - lso);
            }
        }
        // patch vector B
        if (a1) {
            unsigned long long key =
                ((unsigned long long)__float_as_uint(best1) << 32) | (unsigned)bidx1;
            #pragma unroll
            for (int o = 16; o; o >>= 1) {
                unsigned long long k2 = __shfl_down_sync(0xffffffffu, key, o);
                if (k2 < key) key = k2;
            }
            key = __shfl_sync(0xffffffffu, key, 0);
            const int idx = (int)(key & 0xffffffffu);
            const int old = g_idx[nB];
            if (idx != old) {
                if (lane == 0) g_idx[nB] = idx;
                float lsn = 0.f, lso = 0.f;
                if (lane < 16) {
                    float4 e4 = ((const float4*)(emb + (size_t)idx * D))[lane];
                    float4 o4 = ((const float4*)(emb + (size_t)old * D))[lane];
                    float xx = xv1[4*lane], xy = xv1[4*lane+1], xz = xv1[4*lane+2], xw2 = xv1[4*lane+3];
                    float dx = e4.x-xx, dy = e4.y-xy, dz = e4.z-xz, dw = e4.w-xw2;
                    ((float4*)(out + (size_t)nB * D))[lane] =
                        make_float4(xx+dx, xy+dy, xz+dz, xw2+dw);
                    lsn = dx*dx + dy*dy + dz*dz + dw*dw;
                    float ox = o4.x-xx, oy = o4.y-xy, oz = o4.z-xz, ow = o4.w-xw2;
                    lso = ox*ox + oy*oy + oz*oz + ow*ow;
                }
                #pragma unroll
                for (int o = 16; o; o >>= 1) {
                    lsn += __shfl_down_sync(0xffffffffu, lsn, o);
                    lso += __shfl_down_sync(0xffffffffu, lso, o);
                }
                if (lane == 0) atomicAdd(&g_fix, lsn - lso);
            }
        }
    }
}

// ---------------- one-hot encodings: dedicated streaming kernel -----------
__global__ __launch_bounds__(512) void vq_onehot(float* __restrict__ out) {
    __shared__ int sI[64];
    const int r0 = blockIdx.x * 64;       // grid 1024
    if (threadIdx.x < 64) sI[threadIdx.x] = g_idx[r0 + threadIdx.x];
    __syncthreads();
    float* eout = out + OUT_E_OFF;
    #pragma unroll 8
    for (int i = threadIdx.x; i < 64 * 256; i += 512) {
        int r = i >> 8, c4 = i & 255;
        int idx = sI[r];
        float4 v = make_float4(0.f, 0.f, 0.f, 0.f);
        if ((idx >> 2) == c4) ((float*)&v)[idx & 3] = 1.f;
        __stcs(&((float4*)(eout + (size_t)(r0 + r) * K))[c4], v);
    }
}

// ---------------- finalize: 512 partials + fix ----------------------------
__global__ void vq_finalize(float* __restrict__ out) {
    __shared__ double sR[256];
    int tid = threadIdx.x;   // 256
    sR[tid] = (double)g_part2[tid] + (double)g_part2[tid + 256];
    __syncthreads();
    #pragma unroll
    for (int st = 128; st; st >>= 1) {
        if (tid < st) sR[tid] += sR[tid + st];
        __syncthreads();
    }
    if (tid == 0) {
        double tot = sR[0] + (double)g_fix;
        float cb = (float)(tot / (double)((size_t)N_VEC * D));
        out[OUT_S_OFF + 0] = cb + 0.25f * cb;
        out[OUT_S_OFF + 1] = cb;
        out[OUT_S_OFF + 2] = cb;
    }
}

extern "C" void kernel_launch(void* const* d_in, const int* in_sizes, int n_in,
                              void* d_out, int out_size) {
    const float* x   = (const float*)d_in[0];
    const float* emb = (const float*)d_in[1];
    float* out = (float*)d_out;
    cudaFuncSetAttribute(vq_m1, cudaFuncAttributeMaxDynamicSharedMemorySize, SMEM_TOTAL);
    vq_prep<<<8, 128>>>(emb);
    vq_m1<<<NBLK, 512, SMEM_TOTAL>>>(x);
    vq_m2<<<512, 128>>>(x, emb, out);
    vq_fallback<<<FBLOCKS, 256>>>(x, emb, out);
    vq_onehot<<<N_VEC / 64, 512>>>(out);
    vq_finalize<<<1, 256>>>(out);
}

// round 12
// speedup vs baseline: 1.8009x; 1.0704x over previous
#include <cuda_runtime.h>
#include <cuda_fp16.h>
#include <cstdint>
#include <math_constants.h>

#define N_VEC 65536
#define D 64
#define K 1024
#define MTILE 512
#define NBLK (N_VEC / MTILE)       // 128
#define MARGIN 5e-5f
#define OUT_E_OFF ((size_t)N_VEC * D)
#define OUT_S_OFF (OUT_E_OFF + (size_t)N_VEC * K)

#define APAD 72                    // fp16 elems per padded row (144B)
#define BPAD 72
// M1 dynamic smem offsets (bytes)
#define OFF_SB  0                  // 4KB : g_B copy
#define OFF_A   4096               // 512*144 = 73728
#define OFF_B   77824              // 1024*144 = 147456
#define SMEM_TOTAL 225280

__device__ float  g_B[K];
__device__ __align__(16) __half g_ehf[K * BPAD];
__device__ int    g_cnt;
__device__ int    g_list[N_VEC];
__device__ int    g_idx[N_VEC];
__device__ __align__(16) int4 g_cand[N_VEC];
__device__ float  g_part2[512];
__device__ float  g_fix;

// ---- packed orderable key: [31:10] quantized score (orderable-int), [9:0] 1023-k
__device__ __forceinline__ uint32_t packkey(float s, uint32_t kinv) {
    uint32_t b = __float_as_uint(s);
    uint32_t m = (uint32_t)((int)b >> 31) | 0x80000000u;
    return ((b ^ m) & 0xFFFFFC00u) | kinv;
}
__device__ __forceinline__ float unpackkey(uint32_t key) {
    uint32_t ko = key & 0xFFFFFC00u;
    uint32_t m = (ko & 0x80000000u) ? 0x80000000u : 0xFFFFFFFFu;
    return __uint_as_float(ko ^ m);
}
// branchless insert into descending top-4 (7 IMNMX)
#define INSK(S, t0) { uint32_t _t = (t0), _u; \
    _u = max((S)[0], _t); _t = min((S)[0], _t); (S)[0] = _u; \
    _u = max((S)[1], _t); _t = min((S)[1], _t); (S)[1] = _u; \
    _u = max((S)[2], _t); _t = min((S)[2], _t); (S)[2] = _u; \
    (S)[3] = max((S)[3], _t); }

#define MMA(c, a, bb0, bb1) asm volatile( \
    "mma.sync.aligned.m16n8k16.row.col.f32.f16.f16.f32 " \
    "{%0,%1,%2,%3}, {%4,%5,%6,%7}, {%8,%9}, {%0,%1,%2,%3};" \
    : "+f"(c[0]), "+f"(c[1]), "+f"(c[2]), "+f"(c[3]) \
    : "r"(a[0]), "r"(a[1]), "r"(a[2]), "r"(a[3]), "r"(bb0), "r"(bb1))

#define CSWP(a, b) { if ((a) > (b)) { int _t = (a); (a) = (b); (b) = _t; } }

// one MMA step: compute 8 scores for tile NT using B-frags (B0,B1), update S
#define STEP(B0, B1, NT) { \
    float c0[4] = {0.f,0.f,0.f,0.f}, c1[4] = {0.f,0.f,0.f,0.f}; \
    _Pragma("unroll") \
    for (int ks = 0; ks < 4; ks++) { \
        MMA(c0, af[0][ks], (B0)[ks], (B1)[ks]); \
        MMA(c1, af[1][ks], (B0)[ks], (B1)[ks]); \
    } \
    const int k0i = (NT) * 8 + tig * 2; \
    const float Bc0 = sB[k0i], Bc1 = sB[k0i + 1]; \
    const uint32_t kv0 = 1023u - (uint32_t)k0i; \
    const uint32_t kv1 = 1022u - (uint32_t)k0i; \
    INSK(S[0], packkey(fmaf(2.f, c0[0], -Bc0), kv0)); \
    INSK(S[0], packkey(fmaf(2.f, c0[1], -Bc1), kv1)); \
    INSK(S[1], packkey(fmaf(2.f, c0[2], -Bc0), kv0)); \
    INSK(S[1], packkey(fmaf(2.f, c0[3], -Bc1), kv1)); \
    INSK(S[2], packkey(fmaf(2.f, c1[0], -Bc0), kv0)); \
    INSK(S[2], packkey(fmaf(2.f, c1[1], -Bc1), kv1)); \
    INSK(S[3], packkey(fmaf(2.f, c1[2], -Bc0), kv0)); \
    INSK(S[3], packkey(fmaf(2.f, c1[3], -Bc1), kv1)); }

#define LOADB(B0, B1, NT) { \
    const int brw = ((NT) * 8 + g) * 36; \
    _Pragma("unroll") \
    for (int ks = 0; ks < 4; ks++) { \
        (B0)[ks] = Bw[brw + ks * 8 + tig]; \
        (B1)[ks] = Bw[brw + ks * 8 + tig + 4]; \
    } }

// ---------------- prep: g_B (exact chain) + padded fp16 codebook ----------
__global__ void vq_prep(const float* __restrict__ emb) {
    int k = blockIdx.x * blockDim.x + threadIdx.x;    // 8 x 128 = 1024
    float v[D];
    const float4* r4 = (const float4*)(emb + (size_t)k * D);
    #pragma unroll
    for (int j = 0; j < 16; j++) {
        float4 t = r4[j];
        v[4*j] = t.x; v[4*j+1] = t.y; v[4*j+2] = t.z; v[4*j+3] = t.w;
    }
    float bb = 0.f;
    #pragma unroll
    for (int d = 0; d < D; d++) bb += v[d] * v[d];
    g_B[k] = bb;
    __half2* eb = (__half2*)(g_ehf + (size_t)k * BPAD);
    #pragma unroll
    for (int j = 0; j < 32; j++)
        eb[j] = __floats2half2_rn(v[2*j], v[2*j+1]);
    #pragma unroll
    for (int j = 32; j < 36; j++)
        eb[j] = __floats2half2_rn(0.f, 0.f);
    if (k == 0) { g_cnt = 0; g_fix = 0.f; }
}

// ---------------- M1: HMMA(fp16) prefilter, B-frag double buffer ----------
__global__ __launch_bounds__(512, 1) void vq_m1(
    const float* __restrict__ xg)
{
    extern __shared__ char sm[];
    float*    sB = (float*)(sm + OFF_SB);
    uint32_t* Aw = (uint32_t*)(sm + OFF_A);   // 36 words per padded row
    uint32_t* Bw = (uint32_t*)(sm + OFF_B);

    const int tid = threadIdx.x;
    const int warp = tid >> 5, lane = tid & 31;
    const int g = lane >> 2, tig = lane & 3;
    const int n0 = blockIdx.x * MTILE;

    for (int i = tid; i < K; i += 512) sB[i] = g_B[i];
    { // stage A: x f32 -> fp16 padded rows
        const float4* x4 = (const float4*)(xg + (size_t)n0 * D);
        for (int i = tid; i < MTILE * 16; i += 512) {
            float4 v = x4[i];
            int row = i >> 4, j = i & 15;
            __half2* p = (__half2*)((__half*)(sm + OFF_A) + row * APAD + j * 4);
            p[0] = __floats2half2_rn(v.x, v.y);
            p[1] = __floats2half2_rn(v.z, v.w);
        }
    }
    { // stage B: padded fp16 codebook copy
        const float4* e4 = (const float4*)g_ehf;
        float4* s4 = (float4*)(sm + OFF_B);
        for (int i = tid; i < (K * BPAD * 2) / 16; i += 512) s4[i] = e4[i];
    }
    __syncthreads();

    const int rbase = warp * 32;
    // preload A fragments: [rowtile][kstep][4 regs]
    uint32_t af[2][4][4];
    #pragma unroll
    for (int rt = 0; rt < 2; rt++) {
        int r0w = (rbase + rt * 16 + g) * 36;
        #pragma unroll
        for (int ks = 0; ks < 4; ks++) {
            int kw = ks * 8 + tig;
            af[rt][ks][0] = Aw[r0w + kw];
            af[rt][ks][1] = Aw[r0w + 288 + kw];      // +8 rows
            af[rt][ks][2] = Aw[r0w + kw + 4];
            af[rt][ks][3] = Aw[r0w + 288 + kw + 4];
        }
    }
    uint32_t S[4][4];
    #pragma unroll
    for (int j = 0; j < 4; j++)
        #pragma unroll
        for (int p = 0; p < 4; p++) S[j][p] = 0u;

    // register-double-buffered B fragments: prefetch next tile during select
    uint32_t bA0[4], bA1[4], bB0[4], bB1[4];
    LOADB(bA0, bA1, 0);
    #pragma unroll 4
    for (int nt = 0; nt < 128; nt += 2) {
        LOADB(bB0, bB1, nt + 1);
        STEP(bA0, bA1, nt);
        if (nt + 2 < 128) LOADB(bA0, bA1, nt + 2);
        STEP(bB0, bB1, nt + 1);
    }
    // quad merge (lanes in a quad own the same 4 rows, disjoint cols)
    #pragma unroll
    for (int dd = 1; dd <= 2; dd <<= 1) {
        #pragma unroll
        for (int j = 0; j < 4; j++) {
            uint32_t ns[4];
            #pragma unroll
            for (int p = 0; p < 4; p++)
                ns[p] = __shfl_xor_sync(0xffffffffu, S[j][p], dd);
            #pragma unroll
            for (int p = 0; p < 4; p++) INSK(S[j], ns[p]);
        }
    }
    // this thread owns row slot j == tig  (row = g + tig*8 within warp)
    const int rowp = rbase + g + tig * 8;
    const int n = n0 + rowp;
    uint32_t K0 = 0, K1 = 0, K2 = 0, K3 = 0;
    #pragma unroll
    for (int j = 0; j < 4; j++) if (tig == j) {
        K0 = S[j][0]; K1 = S[j][1]; K2 = S[j][2]; K3 = S[j][3];
    }
    const float s0f = unpackkey(K0), s3f = unpackkey(K3);
    const bool fb = (s3f >= s0f - MARGIN);
    int ci[4] = { 1023 - (int)(K0 & 1023u), 1023 - (int)(K1 & 1023u),
                  1023 - (int)(K2 & 1023u), 1023 - (int)(K3 & 1023u) };
    CSWP(ci[0], ci[1]); CSWP(ci[2], ci[3]);
    CSWP(ci[0], ci[2]); CSWP(ci[1], ci[3]); CSWP(ci[1], ci[2]);
    if (fb) { int sl = atomicAdd(&g_cnt, 1); g_list[sl] = n; }
    g_cand[n] = make_int4(ci[0], ci[1], ci[2], ci[3]);
}

// ---------------- M2: exact rescore + quantized_st + loss (high occ) ------
__global__ __launch_bounds__(128) void vq_m2(
    const float* __restrict__ xg, const float* __restrict__ emb, float* __restrict__ out)
{
    __shared__ int   sIdx[128];
    __shared__ float sW[4];
    const int tid = threadIdx.x, lane = tid & 31, warp = tid >> 5;
    const int n0 = blockIdx.x * 128;
    const int n = n0 + tid;

    int4 cd = g_cand[n];
    float xv[64];
    {
        const float4* xr = (const float4*)(xg + (size_t)n * D);
        #pragma unroll
        for (int j = 0; j < 16; j++) {
            float4 v = xr[j];
            xv[4*j] = v.x; xv[4*j+1] = v.y; xv[4*j+2] = v.z; xv[4*j+3] = v.w;
        }
    }
    float Av = 0.f;
    #pragma unroll
    for (int d = 0; d < D; d++) Av = fmaf(xv[d], xv[d], Av);

    int cand[4] = {cd.x, cd.y, cd.z, cd.w};
    float best = CUDART_INF_F; int bidx = 0;
    #pragma unroll
    for (int q = 0; q < 4; q++) {
        int idx = cand[q];
        const float4* er = (const float4*)(emb + (size_t)idx * D);
        float a = 0.f;
        #pragma unroll
        for (int j = 0; j < 16; j++) {
            float4 v = er[j];
            a = fmaf(xv[4*j],   v.x, a);
            a = fmaf(xv[4*j+1], v.y, a);
            a = fmaf(xv[4*j+2], v.z, a);
            a = fmaf(xv[4*j+3], v.w, a);
        }
        float ddv = (Av + g_B[idx]) - 2.f * a;
        if (ddv < best) { best = ddv; bidx = idx; }   // ascending k, strict <
    }
    sIdx[tid] = bidx;
    g_idx[n] = bidx;
    __syncthreads();

    // quantized_st + loss: linear coalesced loop over the 128-vector tile
    float ls = 0.f;
    {
        const float4* x4 = (const float4*)(xg + (size_t)n0 * D);
        float4* qo = (float4*)(out + (size_t)n0 * D);
        #pragma unroll
        for (int it = 0; it < 16; it++) {
            int i = tid + it * 128;
            int r = i >> 4, c4 = i & 15;
            int idx = sIdx[r];
            float4 xw = x4[i];
            float4 e4 = ((const float4*)(emb + (size_t)idx * D))[c4];
            float dx = e4.x - xw.x, dy = e4.y - xw.y;
            float dz = e4.z - xw.z, dw = e4.w - xw.w;
            __stcs(&qo[i], make_float4(xw.x + dx, xw.y + dy, xw.z + dz, xw.w + dw));
            ls += dx*dx + dy*dy + dz*dz + dw*dw;
        }
    }
    #pragma unroll
    for (int o = 16; o; o >>= 1) ls += __shfl_down_sync(0xffffffffu, ls, o);
    if (lane == 0) sW[warp] = ls;
    __syncthreads();
    if (tid == 0) g_part2[blockIdx.x] = sW[0] + sW[1] + sW[2] + sW[3];
}

// ---------------- fallback: chunked smem, 1 vec/warp, MLP loads -----------
#define FCHUNK 128
#define FSTRIDE 68                  // floats per row (16B aligned, conflict-free)
#define FBLOCKS 296                 // 2 blocks/SM
__global__ __launch_bounds__(256) void vq_fallback(
    const float* __restrict__ xg, const float* __restrict__ emb, float* __restrict__ out)
{
    __shared__ float sC[FCHUNK * FSTRIDE];   // 34816B
    const int cnt = g_cnt;
    if (blockIdx.x * 8 >= cnt) return;
    const int tid = threadIdx.x, warp = tid >> 5, lane = tid & 31;
    const int nwg = FBLOCKS * 8;             // 2368 vectors per round
    const int rounds = (cnt + nwg - 1) / nwg;
    for (int rd = 0; rd < rounds; rd++) {
        if (rd * nwg + blockIdx.x * 8 >= cnt) break;
        const int it = rd * nwg + blockIdx.x * 8 + warp;
        const bool act = it < cnt;
        const int n = act ? g_list[it] : 0;
        float xv[64];
        float Av = 0.f;
        if (act) {
            const float4* xr = (const float4*)(xg + (size_t)n * D);
            #pragma unroll
            for (int j = 0; j < 16; j++) {
                float4 v = xr[j];
                xv[4*j] = v.x; xv[4*j+1] = v.y; xv[4*j+2] = v.z; xv[4*j+3] = v.w;
            }
            #pragma unroll
            for (int d = 0; d < D; d++) Av = fmaf(xv[d], xv[d], Av);
        }
        float best = CUDART_INF_F; int bidx = 0;
        for (int ch = 0; ch < K / FCHUNK; ch++) {
            // MLP-batched chunk load: issue all 8 LDG.128 before any STS
            float4 ld[8];
            const float4* e4 = (const float4*)(emb + (size_t)ch * FCHUNK * D);
            #pragma unroll
            for (int u = 0; u < 8; u++) ld[u] = e4[tid + u * 256];
            __syncthreads();      // prev chunk fully consumed
            #pragma unroll
            for (int u = 0; u < 8; u++) {
                int i = tid + u * 256;
                int row = i >> 4, j = i & 15;
                *(float4*)(sC + row * FSTRIDE + j * 4) = ld[u];
            }
            __syncthreads();
            if (act) {
                #pragma unroll
                for (int cj = 0; cj < FCHUNK / 32; cj++) {
                    int c = lane + cj * 32;
                    int k = ch * FCHUNK + c;
                    const float4* er = (const float4*)(sC + c * FSTRIDE);
                    float a = 0.f;
                    #pragma unroll
                    for (int j = 0; j < 16; j++) {
                        float4 v = er[j];
                        a = fmaf(xv[4*j],   v.x, a);
                        a = fmaf(xv[4*j+1], v.y, a);
                        a = fmaf(xv[4*j+2], v.z, a);
                        a = fmaf(xv[4*j+3], v.w, a);
                    }
                    float ddv = (Av + g_B[k]) - 2.f * a;
                    if (ddv < best) { best = ddv; bidx = k; }
                }
            }
        }
        if (act) {
            // warp-min with lowest-k tie-break
            unsigned long long key =
                ((unsigned long long)__float_as_uint(best) << 32) | (unsigned)bidx;
            #pragma unroll
            for (int o = 16; o; o >>= 1) {
                unsigned long long k2 = __shfl_down_sync(0xffffffffu, key, o);
                if (k2 < key) key = k2;
            }
            key = __shfl_sync(0xffffffffu, key, 0);
            const int idx = (int)(key & 0xffffffffu);
            const int old = g_idx[n];
            if (idx != old) {
                if (lane == 0) g_idx[n] = idx;
                float lsn = 0.f, lso = 0.f;
                if (lane < 16) {
                    float4 e4 = ((const float4*)(emb + (size_t)idx * D))[lane];
                    float4 o4 = ((const float4*)(emb + (size_t)old * D))[lane];
                    float xx = xv[4*lane], xy = xv[4*lane+1], xz = xv[4*lane+2], xw2 = xv[4*lane+3];
                    float dx = e4.x-xx, dy = e4.y-xy, dz = e4.z-xz, dw = e4.w-xw2;
                    ((float4*)(out + (size_t)n * D))[lane] =
                        make_float4(xx+dx, xy+dy, xz+dz, xw2+dw);
                    lsn = dx*dx + dy*dy + dz*dz + dw*dw;
                    float ox = o4.x-xx, oy = o4.y-xy, oz = o4.z-xz, ow = o4.w-xw2;
                    lso = ox*ox + oy*oy + oz*oz + ow*ow;
                }
                #pragma unroll
                for (int o = 16; o; o >>= 1) {
                    lsn += __shfl_down_sync(0xffffffffu, lsn, o);
                    lso += __shfl_down_sync(0xffffffffu, lso, o);
                }
                if (lane == 0) atomicAdd(&g_fix, lsn - lso);
            }
        }
    }
}

// ---------------- one-hot encodings: dedicated streaming kernel -----------
__global__ __launch_bounds__(512) void vq_onehot(float* __restrict__ out) {
    __shared__ int sI[64];
    const int r0 = blockIdx.x * 64;       // grid 1024
    if (threadIdx.x < 64) sI[threadIdx.x] = g_idx[r0 + threadIdx.x];
    __syncthreads();
    float* eout = out + OUT_E_OFF;
    #pragma unroll 8
    for (int i = threadIdx.x; i < 64 * 256; i += 512) {
        int r = i >> 8, c4 = i & 255;
        int idx = sI[r];
        float4 v = make_float4(0.f, 0.f, 0.f, 0.f);
        if ((idx >> 2) == c4) ((float*)&v)[idx & 3] = 1.f;
        __stcs(&((float4*)(eout + (size_t)(r0 + r) * K))[c4], v);
    }
}

// ---------------- finalize: 512 partials + fix ----------------------------
__global__ void vq_finalize(float* __restrict__ out) {
    __shared__ double sR[256];
    int tid = threadIdx.x;   // 256
    sR[tid] = (double)g_part2[tid] + (double)g_part2[tid + 256];
    __syncthreads();
    #pragma unroll
    for (int st = 128; st; st >>= 1) {
        if (tid < st) sR[tid] += sR[tid + st];
        __syncthreads();
    }
    if (tid == 0) {
        double tot = sR[0] + (double)g_fix;
        float cb = (float)(tot / (double)((size_t)N_VEC * D));
        out[OUT_S_OFF + 0] = cb + 0.25f * cb;
        out[OUT_S_OFF + 1] = cb;
        out[OUT_S_OFF + 2] = cb;
    }
}

extern "C" void kernel_launch(void* const* d_in, const int* in_sizes, int n_in,
                              void* d_out, int out_size) {
    const float* x   = (const float*)d_in[0];
    const float* emb = (const float*)d_in[1];
    float* out = (float*)d_out;
    cudaFuncSetAttribute(vq_m1, cudaFuncAttributeMaxDynamicSharedMemorySize, SMEM_TOTAL);
    vq_prep<<<8, 128>>>(emb);
    vq_m1<<<NBLK, 512, SMEM_TOTAL>>>(x);
    vq_m2<<<512, 128>>>(x, emb, out);
    vq_fallback<<<FBLOCKS, 256>>>(x, emb, out);
    vq_onehot<<<N_VEC / 64, 512>>>(out);
    vq_finalize<<<1, 256>>>(out);
}

// round 13
// speedup vs baseline: 1.8287x; 1.0154x over previous
#include <cuda_runtime.h>
#include <cuda_fp16.h>
#include <cstdint>
#include <math_constants.h>

#define N_VEC 65536
#define D 64
#define K 1024
#define MARGIN 5e-4f
#define OUT_E_OFF ((size_t)N_VEC * D)
#define OUT_S_OFF (OUT_E_OFF + (size_t)N_VEC * K)

#define APAD 72                    // fp16 elems per padded row (144B)
#define BPAD 72
// M1 smem layout (per CTA, 2 CTAs/SM): sBb 2KB | A 256*144 | B 512*144
#define OFF_SBB 0
#define OFF_A   2048
#define OFF_B   (2048 + 36864)     // 38912
#define SMEM_TOTAL (OFF_B + 73728) // 112640

__device__ float  g_B[K];
__device__ __align__(16) __half g_ehf[K * BPAD];
__device__ int    g_cnt;
__device__ int    g_list[N_VEC];
__device__ int    g_idx[N_VEC];
__device__ __align__(16) uint4 g_k4[2][N_VEC];  // per-half sorted top-4 keys
__device__ float  g_part2[512];
__device__ float  g_fix;

// key: biased score (+1.0 => positive => raw-bit orderable), low 10 bits = 1023-k
__device__ __forceinline__ float unpackkey(uint32_t key) {
    return __uint_as_float(key & 0xFFFFFC00u);
}
// branchless insert into descending top-4 (7 IMNMX)
#define INSK(S, t0) { uint32_t _t = (t0), _u; \
    _u = max((S)[0], _t); _t = min((S)[0], _t); (S)[0] = _u; \
    _u = max((S)[1], _t); _t = min((S)[1], _t); (S)[1] = _u; \
    _u = max((S)[2], _t); _t = min((S)[2], _t); (S)[2] = _u; \
    (S)[3] = max((S)[3], _t); }

#define MMA(c, a, bb0, bb1) asm volatile( \
    "mma.sync.aligned.m16n8k16.row.col.f32.f16.f16.f32 " \
    "{%0,%1,%2,%3}, {%4,%5,%6,%7}, {%8,%9}, {%0,%1,%2,%3};" \
    : "+f"(c[0]), "+f"(c[1]), "+f"(c[2]), "+f"(c[3]) \
    : "r"(a[0]), "r"(a[1]), "r"(a[2]), "r"(a[3]), "r"(bb0), "r"(bb1))

#define CSWP(a, b) { if ((a) > (b)) { int _t = (a); (a) = (b); (b) = _t; } }

#define LOADB(B0, B1, NT) { \
    const int brw = ((NT) * 8 + g) * 36; \
    _Pragma("unroll") \
    for (int ks = 0; ks < 4; ks++) { \
        (B0)[ks] = Bw[brw + ks * 8 + tig]; \
        (B1)[ks] = Bw[brw + ks * 8 + tig + 4]; \
    } }

// one step: 4 MMAs over ks, 4 scores (rows g, g+8 x 2 cols), cheap-pack, insert
#define STEP(B0, B1, NT) { \
    float c[4] = {0.f, 0.f, 0.f, 0.f}; \
    _Pragma("unroll") \
    for (int ks = 0; ks < 4; ks++) MMA(c, af[ks], (B0)[ks], (B1)[ks]); \
    const int k0l = (NT) * 8 + tig * 2; \
    const float2 bb = *(const float2*)(sBb + k0l); \
    const uint32_t kv0 = kvbase - (uint32_t)k0l; \
    float s; uint32_t key; \
    s = fmaf(2.f, c[0], bb.x); key = (__float_as_uint(s) & 0xFFFFFC00u) | kv0;       INSK(S[0], key); \
    s = fmaf(2.f, c[1], bb.y); key = (__float_as_uint(s) & 0xFFFFFC00u) | (kv0 - 1); INSK(S[0], key); \
    s = fmaf(2.f, c[2], bb.x); key = (__float_as_uint(s) & 0xFFFFFC00u) | kv0;       INSK(S[1], key); \
    s = fmaf(2.f, c[3], bb.y); key = (__float_as_uint(s) & 0xFFFFFC00u) | (kv0 - 1); INSK(S[1], key); }

// ---------------- prep: g_B (exact chain) + padded fp16 codebook ----------
__global__ void vq_prep(const float* __restrict__ emb) {
    int k = blockIdx.x * blockDim.x + threadIdx.x;    // 8 x 128 = 1024
    float v[D];
    const float4* r4 = (const float4*)(emb + (size_t)k * D);
    #pragma unroll
    for (int j = 0; j < 16; j++) {
        float4 t = r4[j];
        v[4*j] = t.x; v[4*j+1] = t.y; v[4*j+2] = t.z; v[4*j+3] = t.w;
    }
    float bb = 0.f;
    #pragma unroll
    for (int d = 0; d < D; d++) bb += v[d] * v[d];
    g_B[k] = bb;
    __half2* eb = (__half2*)(g_ehf + (size_t)k * BPAD);
    #pragma unroll
    for (int j = 0; j < 32; j++)
        eb[j] = __floats2half2_rn(v[2*j], v[2*j+1]);
    #pragma unroll
    for (int j = 32; j < 36; j++)
        eb[j] = __floats2half2_rn(0.f, 0.f);
    if (k == 0) { g_cnt = 0; g_fix = 0.f; }
}

// ---------------- M1: K-split HMMA prefilter, 2 CTAs/SM -------------------
// CTA = (n-tile of 256 vectors) x (half of 512 codes). Writes sorted top-4 keys.
__global__ __launch_bounds__(512, 2) void vq_m1(
    const float* __restrict__ xg)
{
    extern __shared__ char sm[];
    float*    sBb = (float*)(sm + OFF_SBB);
    uint32_t* Aw  = (uint32_t*)(sm + OFF_A);   // 36 words per padded row
    uint32_t* Bw  = (uint32_t*)(sm + OFF_B);

    const int tid = threadIdx.x;
    const int warp = tid >> 5, lane = tid & 31;
    const int g = lane >> 2, tig = lane & 3;
    const int bid = blockIdx.x;
    const int n0 = (bid >> 1) * 256;
    const int kh = bid & 1;
    const uint32_t kvbase = 1023u - (uint32_t)(kh * 512);

    // stage biased B-norms for this half: sBb[i] = 1.0f - ||e||^2
    if (tid < 512) sBb[tid] = 1.0f - g_B[kh * 512 + tid];
    { // stage A: 256 rows of x -> fp16 padded
        const float4* x4 = (const float4*)(xg + (size_t)n0 * D);
        #pragma unroll
        for (int u = 0; u < 8; u++) {
            int i = tid + u * 512;
            float4 v = x4[i];
            int row = i >> 4, j = i & 15;
            __half2* p = (__half2*)((__half*)(sm + OFF_A) + row * APAD + j * 4);
            p[0] = __floats2half2_rn(v.x, v.y);
            p[1] = __floats2half2_rn(v.z, v.w);
        }
    }
    { // stage B: this half's 512 codebook rows (already fp16-padded)
        const float4* e4 = (const float4*)(g_ehf + (size_t)kh * 512 * BPAD);
        float4* s4 = (float4*)(sm + OFF_B);
        #pragma unroll
        for (int u = 0; u < 9; u++) {
            int i = tid + u * 512;
            s4[i] = e4[i];
        }
    }
    __syncthreads();

    // A fragments: this warp's 16 rows (rbase..rbase+15)
    const int rbase = warp * 16;
    uint32_t af[4][4];
    {
        int r0w = (rbase + g) * 36;
        #pragma unroll
        for (int ks = 0; ks < 4; ks++) {
            int kw = ks * 8 + tig;
            af[ks][0] = Aw[r0w + kw];
            af[ks][1] = Aw[r0w + 288 + kw];      // +8 rows
            af[ks][2] = Aw[r0w + kw + 4];
            af[ks][3] = Aw[r0w + 288 + kw + 4];
        }
    }
    uint32_t S[2][4];
    #pragma unroll
    for (int j = 0; j < 2; j++)
        #pragma unroll
        for (int p = 0; p < 4; p++) S[j][p] = 0u;

    // register-double-buffered B fragments over 64 local tiles
    uint32_t bA0[4], bA1[4], bB0[4], bB1[4];
    LOADB(bA0, bA1, 0);
    #pragma unroll 2
    for (int nt = 0; nt < 64; nt += 2) {
        LOADB(bB0, bB1, nt + 1);
        STEP(bA0, bA1, nt);
        if (nt + 2 < 64) LOADB(bA0, bA1, nt + 2);
        STEP(bB0, bB1, nt + 1);
    }
    // quad merge (4 lanes of a quad cover disjoint cols of the same 2 rows)
    #pragma unroll
    for (int dd = 1; dd <= 2; dd <<= 1) {
        #pragma unroll
        for (int j = 0; j < 2; j++) {
            uint32_t ns[4];
            #pragma unroll
            for (int p = 0; p < 4; p++)
                ns[p] = __shfl_xor_sync(0xffffffffu, S[j][p], dd);
            #pragma unroll
            for (int p = 0; p < 4; p++) INSK(S[j], ns[p]);
        }
    }
    // owners: tig 0 -> row g (slot 0), tig 1 -> row g+8 (slot 1)
    if (tig < 2) {
        const int r = rbase + g + tig * 8;
        const int n = n0 + r;
        uint32_t* Ss = S[tig];
        g_k4[kh][n] = make_uint4(Ss[0], Ss[1], Ss[2], Ss[3]);
    }
}

// ---------------- M2: merge halves + exact rescore + epilogue -------------
__global__ __launch_bounds__(128) void vq_m2(
    const float* __restrict__ xg, const float* __restrict__ emb, float* __restrict__ out)
{
    __shared__ int   sIdx[128];
    __shared__ float sW[4];
    const int tid = threadIdx.x, lane = tid & 31, warp = tid >> 5;
    const int n0 = blockIdx.x * 128;
    const int n = n0 + tid;

    // merge the two per-half sorted top-4s -> global top-4
    uint4 ka = g_k4[0][n], kb = g_k4[1][n];
    uint32_t S[4] = {ka.x, ka.y, ka.z, ka.w};
    INSK(S, kb.x); INSK(S, kb.y); INSK(S, kb.z); INSK(S, kb.w);
    const float s0f = unpackkey(S[0]), s3f = unpackkey(S[3]);
    const bool fb = (s3f >= s0f - MARGIN);
    int ci[4] = { 1023 - (int)(S[0] & 1023u), 1023 - (int)(S[1] & 1023u),
                  1023 - (int)(S[2] & 1023u), 1023 - (int)(S[3] & 1023u) };
    CSWP(ci[0], ci[1]); CSWP(ci[2], ci[3]);
    CSWP(ci[0], ci[2]); CSWP(ci[1], ci[3]); CSWP(ci[1], ci[2]);
    if (fb) { int sl = atomicAdd(&g_cnt, 1); g_list[sl] = n; }

    float xv[64];
    {
        const float4* xr = (const float4*)(xg + (size_t)n * D);
        #pragma unroll
        for (int j = 0; j < 16; j++) {
            float4 v = xr[j];
            xv[4*j] = v.x; xv[4*j+1] = v.y; xv[4*j+2] = v.z; xv[4*j+3] = v.w;
        }
    }
    float Av = 0.f;
    #pragma unroll
    for (int d = 0; d < D; d++) Av = fmaf(xv[d], xv[d], Av);

    // exact rescore (validated round-0 fl chain, ascending-k strict <)
    float best = CUDART_INF_F; int bidx = 0;
    #pragma unroll
    for (int q = 0; q < 4; q++) {
        int idx = ci[q];
        const float4* er = (const float4*)(emb + (size_t)idx * D);
        float a = 0.f;
        #pragma unroll
        for (int j = 0; j < 16; j++) {
            float4 v = er[j];
            a = fmaf(xv[4*j],   v.x, a);
            a = fmaf(xv[4*j+1], v.y, a);
            a = fmaf(xv[4*j+2], v.z, a);
            a = fmaf(xv[4*j+3], v.w, a);
        }
        float ddv = (Av + g_B[idx]) - 2.f * a;
        if (ddv < best) { best = ddv; bidx = idx; }
    }
    sIdx[tid] = bidx;
    g_idx[n] = bidx;
    __syncthreads();

    // quantized_st + loss: linear coalesced loop over the 128-vector tile
    float ls = 0.f;
    {
        const float4* x4 = (const float4*)(xg + (size_t)n0 * D);
        float4* qo = (float4*)(out + (size_t)n0 * D);
        #pragma unroll
        for (int it = 0; it < 16; it++) {
            int i = tid + it * 128;
            int r = i >> 4, c4 = i & 15;
            int idx = sIdx[r];
            float4 xw = x4[i];
            float4 e4 = ((const float4*)(emb + (size_t)idx * D))[c4];
            float dx = e4.x - xw.x, dy = e4.y - xw.y;
            float dz = e4.z - xw.z, dw = e4.w - xw.w;
            __stcs(&qo[i], make_float4(xw.x + dx, xw.y + dy, xw.z + dz, xw.w + dw));
            ls += dx*dx + dy*dy + dz*dz + dw*dw;
        }
    }
    #pragma unroll
    for (int o = 16; o; o >>= 1) ls += __shfl_down_sync(0xffffffffu, ls, o);
    if (lane == 0) sW[warp] = ls;
    __syncthreads();
    if (tid == 0) g_part2[blockIdx.x] = sW[0] + sW[1] + sW[2] + sW[3];
}

// ---------------- fallback: chunked smem, 1 vec/warp, MLP loads -----------
#define FCHUNK 128
#define FSTRIDE 68
#define FBLOCKS 296
__global__ __launch_bounds__(256) void vq_fallback(
    const float* __restrict__ xg, const float* __restrict__ emb, float* __restrict__ out)
{
    __shared__ float sC[FCHUNK * FSTRIDE];   // 34816B
    const int cnt = g_cnt;
    if (blockIdx.x * 8 >= cnt) return;
    const int tid = threadIdx.x, warp = tid >> 5, lane = tid & 31;
    const int nwg = FBLOCKS * 8;
    const int rounds = (cnt + nwg - 1) / nwg;
    for (int rd = 0; rd < rounds; rd++) {
        if (rd * nwg + blockIdx.x * 8 >= cnt) break;
        const int it = rd * nwg + blockIdx.x * 8 + warp;
        const bool act = it < cnt;
        const int n = act ? g_list[it] : 0;
        float xv[64];
        float Av = 0.f;
        if (act) {
            const float4* xr = (const float4*)(xg + (size_t)n * D);
            #pragma unroll
            for (int j = 0; j < 16; j++) {
                float4 v = xr[j];
                xv[4*j] = v.x; xv[4*j+1] = v.y; xv[4*j+2] = v.z; xv[4*j+3] = v.w;
            }
            #pragma unroll
            for (int d = 0; d < D; d++) Av = fmaf(xv[d], xv[d], Av);
        }
        float best = CUDART_INF_F; int bidx = 0;
        for (int ch = 0; ch < K / FCHUNK; ch++) {
            float4 ld[8];
            const float4* e4 = (const float4*)(emb + (size_t)ch * FCHUNK * D);
            #pragma unroll
            for (int u = 0; u < 8; u++) ld[u] = e4[tid + u * 256];
            __syncthreads();
            #pragma unroll
            for (int u = 0; u < 8; u++) {
                int i = tid + u * 256;
                int row = i >> 4, j = i & 15;
                *(float4*)(sC + row * FSTRIDE + j * 4) = ld[u];
            }
            __syncthreads();
            if (act) {
                #pragma unroll
                for (int cj = 0; cj < FCHUNK / 32; cj++) {
                    int c = lane + cj * 32;
                    int k = ch * FCHUNK + c;
                    const float4* er = (const float4*)(sC + c * FSTRIDE);
                    float a = 0.f;
                    #pragma unroll
                    for (int j = 0; j < 16; j++) {
                        float4 v = er[j];
                        a = fmaf(xv[4*j],   v.x, a);
                        a = fmaf(xv[4*j+1], v.y, a);
                        a = fmaf(xv[4*j+2], v.z, a);
                        a = fmaf(xv[4*j+3], v.w, a);
                    }
                    float ddv = (Av + g_B[k]) - 2.f * a;
                    if (ddv < best) { best = ddv; bidx = k; }
                }
            }
        }
        if (act) {
            unsigned long long key =
                ((unsigned long long)__float_as_uint(best) << 32) | (unsigned)bidx;
            #pragma unroll
            for (int o = 16; o; o >>= 1) {
                unsigned long long k2 = __shfl_down_sync(0xffffffffu, key, o);
                if (k2 < key) key = k2;
            }
            key = __shfl_sync(0xffffffffu, key, 0);
            const int idx = (int)(key & 0xffffffffu);
            const int old = g_idx[n];
            if (idx != old) {
                if (lane == 0) g_idx[n] = idx;
                float lsn = 0.f, lso = 0.f;
                if (lane < 16) {
                    float4 e4 = ((const float4*)(emb + (size_t)idx * D))[lane];
                    float4 o4 = ((const float4*)(emb + (size_t)old * D))[lane];
                    float xx = xv[4*lane], xy = xv[4*lane+1], xz = xv[4*lane+2], xw2 = xv[4*lane+3];
                    float dx = e4.x-xx, dy = e4.y-xy, dz = e4.z-xz, dw = e4.w-xw2;
                    ((float4*)(out + (size_t)n * D))[lane] =
                        make_float4(xx+dx, xy+dy, xz+dz, xw2+dw);
                    lsn = dx*dx + dy*dy + dz*dz + dw*dw;
                    float ox = o4.x-xx, oy = o4.y-xy, oz = o4.z-xz, ow = o4.w-xw2;
                    lso = ox*ox + oy*oy + oz*oz + ow*ow;
                }
                #pragma unroll
                for (int o = 16; o; o >>= 1) {
                    lsn += __shfl_down_sync(0xffffffffu, lsn, o);
                    lso += __shfl_down_sync(0xffffffffu, lso, o);
                }
                if (lane == 0) atomicAdd(&g_fix, lsn - lso);
            }
        }
    }
}

// ---------------- one-hot encodings: dedicated streaming kernel -----------
__global__ __launch_bounds__(512) void vq_onehot(float* __restrict__ out) {
    __shared__ int sI[64];
    const int r0 = blockIdx.x * 64;       // grid 1024
    if (threadIdx.x < 64) sI[threadIdx.x] = g_idx[r0 + threadIdx.x];
    __syncthreads();
    float* eout = out + OUT_E_OFF;
    #pragma unroll 8
    for (int i = threadIdx.x; i < 64 * 256; i += 512) {
        int r = i >> 8, c4 = i & 255;
        int idx = sI[r];
        float4 v = make_float4(0.f, 0.f, 0.f, 0.f);
        if ((idx >> 2) == c4) ((float*)&v)[idx & 3] = 1.f;
        __stcs(&((float4*)(eout + (size_t)(r0 + r) * K))[c4], v);
    }
}

// ---------------- finalize: 512 partials + fix ----------------------------
__global__ void vq_finalize(float* __restrict__ out) {
    __shared__ double sR[256];
    int tid = threadIdx.x;   // 256
    sR[tid] = (double)g_part2[tid] + (double)g_part2[tid + 256];
    __syncthreads();
    #pragma unroll
    for (int st = 128; st; st >>= 1) {
        if (tid < st) sR[tid] += sR[tid + st];
        __syncthreads();
    }
    if (tid == 0) {
        double tot = sR[0] + (double)g_fix;
        float cb = (float)(tot / (double)((size_t)N_VEC * D));
        out[OUT_S_OFF + 0] = cb + 0.25f * cb;
        out[OUT_S_OFF + 1] = cb;
        out[OUT_S_OFF + 2] = cb;
    }
}

extern "C" void kernel_launch(void* const* d_in, const int* in_sizes, int n_in,
                              void* d_out, int out_size) {
    const float* x   = (const float*)d_in[0];
    const float* emb = (const float*)d_in[1];
    float* out = (float*)d_out;
    cudaFuncSetAttribute(vq_m1, cudaFuncAttributeMaxDynamicSharedMemorySize, SMEM_TOTAL);
    vq_prep<<<8, 128>>>(emb);
    vq_m1<<<512, 512, SMEM_TOTAL>>>(x);
    vq_m2<<<512, 128>>>(x, emb, out);
    vq_fallback<<<FBLOCKS, 256>>>(x, emb, out);
    vq_onehot<<<N_VEC / 64, 512>>>(out);
    vq_finalize<<<1, 256>>>(out);
}